// round 7
// baseline (speedup 1.0000x reference)
#include <cuda_runtime.h>
#include <math.h>

#define NPTS 8192
#define KNB  32
#define CH   64
#define NEGV (-1e30f)

// ---------------- scratch (device globals; no allocation) ----------------
static __device__ float4 g_p4s[NPTS];                // (x, y, z, |p|^2) unscaled
static __device__ float  g_pos4[NPTS * 4];           // (x/s, y/s, z/s, refl)
static __device__ int    g_batch[NPTS];
static __device__ int    g_bstart[6];
static __device__ int    g_nbr[NPTS * KNB];
static __device__ float  g_nbrd2[NPTS * KNB];
static __device__ int    g_cnt[NPTS];
static __device__ float  g_h[NPTS * KNB * CH];       // 64 MB scratch (valid slots only)
static __device__ float  g_sum[CH];
static __device__ float  g_sumsq[CH];
static __device__ float  g_mean[CH];
static __device__ float  g_A[CH];
static __device__ float  g_Bc[CH];
static __device__ unsigned int g_edges;

// output layout: out[N,64] | pos[N,3] | batch[N] | reflectance[N] | sf[4]
#define POS_OFF   (NPTS * CH)
#define BATCH_OFF (POS_OFF + NPTS * 3)
#define REF_OFF   (BATCH_OFF + NPTS)
#define SF_OFF    (REF_OFF + NPTS)
#define TOTAL_OUT (SF_OFF + 4)

// ---------------- init ----------------
__global__ void k_init() {
    int t = threadIdx.x;
    if (t < CH) { g_sum[t] = 0.0f; g_sumsq[t] = 0.0f; }
    if (t < 6)  g_bstart[t] = NPTS;
    if (t == 0) g_edges = 0u;
}

// decode batch element robustly (int32 / int64 / float32-converted)
__device__ __forceinline__ int decode_batch(const int* braw, int i) {
    int last = braw[NPTS - 1];
    int b;
    if (last == 0) {
        b = braw[2 * i];                   // int64 little-endian, low words
    } else if (last >= 1 && last <= 8) {
        b = braw[i];                       // int32
    } else {
        b = (int)__int_as_float(braw[i]);  // stored as float
    }
    if (b < 0) b = 0;
    if (b > 4) b = 4;
    return b;
}

// ---------------- prep: batch decode, packed pos, pos4, batch starts ----------------
__global__ void k_prep(const float* __restrict__ pos,
                       const float* __restrict__ refl,
                       const float* __restrict__ sf,
                       const int*   __restrict__ braw) {
    int i = blockIdx.x * blockDim.x + threadIdx.x;
    if (i >= NPTS) return;
    int b = decode_batch(braw, i);
    g_batch[i] = b;
    atomicMin(&g_bstart[b], i);
    float x = pos[3 * i + 0];
    float y = pos[3 * i + 1];
    float z = pos[3 * i + 2];
    float sq = fmaf(x, x, fmaf(y, y, z * z));
    g_p4s[i] = make_float4(x, y, z, sq);
    float sc = sf[b < 4 ? b : 3];
    g_pos4[4 * i + 0] = x / sc;
    g_pos4[4 * i + 1] = y / sc;
    g_pos4[4 * i + 2] = z / sc;
    g_pos4[4 * i + 3] = refl[i];
}

__global__ void k_fix() {
    // suffix-min so g_bstart[b] = first index with batch >= b
    if (threadIdx.x == 0) {
        g_bstart[5] = NPTS;
        for (int v = 4; v >= 0; v--) {
            int a = g_bstart[v], b = g_bstart[v + 1];
            g_bstart[v] = a < b ? a : b;
        }
    }
}

// ---------------- neighbor search: smem-tiled candidate scan ----------------
__global__ void __launch_bounds__(256) k_nbr() {
    __shared__ float4 tile[256];
    __shared__ int s_lo, s_hi;
    int tid = threadIdx.x;
    int i   = blockIdx.x * 256 + tid;
    const float RR = (float)((0.02 * 2.1) * (0.02 * 2.1));

    int b  = g_batch[i];
    int lo = g_bstart[b];
    int hi = g_bstart[b + 1];
    // block-wide candidate range: batch is sorted, so it is the union of the
    // first and last thread's ranges.
    if (tid == 0)   s_lo = g_bstart[g_batch[blockIdx.x * 256]];
    if (tid == 255) s_hi = hi;
    __syncthreads();
    int LO = s_lo, HI = s_hi;

    float4 me = g_p4s[i];
    int cnt = 0;
    int base = i * KNB;

    for (int t0 = LO; t0 < HI; t0 += 256) {
        int j = t0 + tid;
        if (j < HI) tile[tid] = g_p4s[j];
        __syncthreads();
        int lim = HI - t0; if (lim > 256) lim = 256;
        // restrict to this thread's own batch range
        int u0 = lo - t0;      if (u0 < 0)   u0 = 0;
        int u1 = hi - t0;      if (u1 > lim) u1 = lim;
        for (int u = u0; u < u1; u++) {
            float4 c = tile[u];
            float dot = fmaf(me.x, c.x, fmaf(me.y, c.y, me.z * c.z));
            float d2  = (me.w + c.w) - 2.0f * dot;
            if (d2 < RR) {
                int jj = t0 + u;
                if (cnt < KNB) {
                    g_nbr[base + cnt]   = jj;
                    g_nbrd2[base + cnt] = d2;
                    cnt++;
                } else {
                    // replace lexicographically-largest (d2, idx); matches stable top_k
                    int   mxs = 0;
                    float mxd = g_nbrd2[base];
                    int   mxi = g_nbr[base];
                    for (int t = 1; t < KNB; t++) {
                        float d  = g_nbrd2[base + t];
                        int   id = g_nbr[base + t];
                        if (d > mxd || (d == mxd && id > mxi)) { mxd = d; mxi = id; mxs = t; }
                    }
                    if (d2 < mxd) {
                        g_nbr[base + mxs]   = jj;
                        g_nbrd2[base + mxs] = d2;
                    }
                }
            }
        }
        __syncthreads();
    }
    g_cnt[i] = cnt;
    atomicAdd(&g_edges, (unsigned int)cnt);
}

// ---------------- edge MLP + sum accumulation ----------------
__global__ void __launch_bounds__(64) k_mlp(const float* __restrict__ x,
                                            const float* __restrict__ w1,
                                            const float* __restrict__ b1,
                                            const float* __restrict__ w2,
                                            const float* __restrict__ b2) {
    int i = blockIdx.x;
    int c = threadIdx.x;
    __shared__ float featsm[8];
    __shared__ float h1sm[CH];

    int cnt = g_cnt[i];

    float w1c[8];
#pragma unroll
    for (int f = 0; f < 8; f++) w1c[f] = w1[f * CH + c];
    float w2c[CH];
#pragma unroll
    for (int f = 0; f < CH; f++) w2c[f] = w2[f * CH + c];
    float b1c = b1[c];
    float b2c = b2[c];

    float p4i0 = g_pos4[4 * i + 0];
    float p4i1 = g_pos4[4 * i + 1];
    float p4i2 = g_pos4[4 * i + 2];
    float p4i3 = g_pos4[4 * i + 3];

    float acc = 0.0f;
    for (int k = 0; k < cnt; k++) {
        int j = g_nbr[i * KNB + k];
        if (c < 4) {
            featsm[c] = x[j * 4 + c];
        } else if (c < 8) {
            int f = c - 4;
            float pi = (f == 0) ? p4i0 : (f == 1) ? p4i1 : (f == 2) ? p4i2 : p4i3;
            featsm[c] = g_pos4[j * 4 + f] - pi;
        }
        __syncthreads();
        float h = b1c;
#pragma unroll
        for (int f = 0; f < 8; f++) h = fmaf(featsm[f], w1c[f], h);
        h = (h >= 0.0f) ? h : 0.01f * h;
        h1sm[c] = h;
        __syncthreads();
        float h2 = b2c;
#pragma unroll
        for (int f = 0; f < CH; f++) h2 = fmaf(h1sm[f], w2c[f], h2);
        h2 = (h2 >= 0.0f) ? h2 : 0.01f * h2;
        g_h[(i * KNB + k) * CH + c] = h2;
        acc += h2;
        __syncthreads();
    }
    if (cnt > 0) atomicAdd(&g_sum[c], acc);
}

// ---------------- mean ----------------
__global__ void k_mean() {
    int c = threadIdx.x;
    if (c < CH) g_mean[c] = g_sum[c] / (float)g_edges;
}

// ---------------- sum of squared deviations ----------------
__global__ void k_sumsq() {
    int t = threadIdx.x;
    int c = t & 63;
    int r = t >> 6;          // 0..3
    float mean = g_mean[c];
    float acc = 0.0f;
    int base = blockIdx.x * 32;
    for (int pi = 0; pi < 32; pi++) {
        int i = base + pi;
        int cnt = g_cnt[i];
        for (int k = r; k < cnt; k += 4) {
            float v = g_h[(i * KNB + k) * CH + c] - mean;
            acc = fmaf(v, v, acc);
        }
    }
    __shared__ float red[256];
    red[t] = acc;
    __syncthreads();
    if (r == 0) {
        float s = red[c] + red[64 + c] + red[128 + c] + red[192 + c];
        atomicAdd(&g_sumsq[c], s);
    }
}

// ---------------- affine coefficients ----------------
__global__ void k_ab(const float* __restrict__ gamma,
                     const float* __restrict__ beta) {
    int c = threadIdx.x;
    if (c < CH) {
        float var = g_sumsq[c] / (float)g_edges;
        float inv = 1.0f / sqrtf(var + 1e-5f);
        float A = gamma[c] * inv;
        g_A[c]  = A;
        g_Bc[c] = beta[c] - g_mean[c] * A;
    }
}

// ---------------- normalize + max-aggregate ----------------
__global__ void __launch_bounds__(64) k_out(float* __restrict__ out) {
    int i = blockIdx.x;
    int c = threadIdx.x;
    int cnt = g_cnt[i];
    float A = g_A[c], B = g_Bc[c];
    float m = NEGV;
    for (int k = 0; k < cnt; k++) {
        float v = fmaf(g_h[(i * KNB + k) * CH + c], A, B);
        m = fmaxf(m, v);
    }
    out[i * CH + c] = m;
}

// ---------------- tuple passthrough ----------------
__global__ void k_pass(float* __restrict__ out,
                       const float* __restrict__ pos,
                       const float* __restrict__ refl,
                       const float* __restrict__ sf) {
    int idx = blockIdx.x * blockDim.x + threadIdx.x;
    if (idx < 3 * NPTS) {
        out[POS_OFF + idx] = pos[idx];
    } else if (idx < 4 * NPTS) {
        int j = idx - 3 * NPTS;
        out[BATCH_OFF + j] = (float)g_batch[j];
    } else if (idx < 5 * NPTS) {
        int j = idx - 4 * NPTS;
        out[REF_OFF + j] = refl[j];
    } else if (idx < 5 * NPTS + 4) {
        int j = idx - 5 * NPTS;
        out[SF_OFF + j] = sf[j];
    }
}

extern "C" void kernel_launch(void* const* d_in, const int* in_sizes, int n_in,
                              void* d_out, int out_size) {
    const float* x     = (const float*)d_in[0];
    const float* pos   = (const float*)d_in[1];
    const float* refl  = (const float*)d_in[2];
    const float* sf    = (const float*)d_in[3];
    const float* w1    = (const float*)d_in[4];
    const float* b1    = (const float*)d_in[5];
    const float* w2    = (const float*)d_in[6];
    const float* b2    = (const float*)d_in[7];
    const float* gamma = (const float*)d_in[8];
    const float* beta  = (const float*)d_in[9];
    const int*   braw  = (const int*)d_in[10];
    float* out = (float*)d_out;

    k_init<<<1, 64>>>();
    k_prep<<<NPTS / 256, 256>>>(pos, refl, sf, braw);
    k_fix<<<1, 32>>>();
    k_nbr<<<NPTS / 256, 256>>>();
    k_mlp<<<NPTS, 64>>>(x, w1, b1, w2, b2);
    k_mean<<<1, 64>>>();
    k_sumsq<<<NPTS / 32, 256>>>();
    k_ab<<<1, 64>>>(gamma, beta);
    k_out<<<NPTS, 64>>>(out);
    if (out_size >= TOTAL_OUT) {
        k_pass<<<(5 * NPTS + 4 + 255) / 256, 256>>>(out, pos, refl, sf);
    }
}

// round 9
// speedup vs baseline: 1.8721x; 1.8721x over previous
#include <cuda_runtime.h>
#include <math.h>

#define NPTS 8192
#define KNB  32
#define CH   64
#define NEGV (-1e30f)

#define NC1     8                 // cells per dim
#define NCELLS  (4 * NC1 * NC1 * NC1)   // 2048 (4 batches)
#define INV_CS  20.0f             // 1 / 0.05 ; 0.05 > R = 0.042

// ---------------- scratch (device globals; no allocation) ----------------
static __device__ float4 g_p4s[NPTS];                // (x, y, z, |p|^2) unscaled
static __device__ float  g_pos4[NPTS * 4];           // (x/s, y/s, z/s, refl)
static __device__ int    g_batch[NPTS];
static __device__ int    g_nbr[NPTS * KNB];
static __device__ float  g_nbrd2[NPTS * KNB];
static __device__ int    g_cnt[NPTS];
static __device__ float  g_h[NPTS * KNB * CH];       // 64 MB scratch (valid slots only)
static __device__ float  g_sum[CH];
static __device__ float  g_sumsq[CH];
static __device__ float  g_mean[CH];
static __device__ float  g_A[CH];
static __device__ float  g_Bc[CH];
static __device__ unsigned int g_edges;
// cell-list structures
static __device__ int    g_cellcnt[NCELLS];
static __device__ int    g_cellstart[NCELLS + 1];
static __device__ int    g_ptcell[NPTS];
static __device__ int    g_ptslot[NPTS];
static __device__ int    g_perm[NPTS];

// output layout: out[N,64] | pos[N,3] | batch[N] | reflectance[N] | sf[4]
#define POS_OFF   (NPTS * CH)
#define BATCH_OFF (POS_OFF + NPTS * 3)
#define REF_OFF   (BATCH_OFF + NPTS)
#define SF_OFF    (REF_OFF + NPTS)
#define TOTAL_OUT (SF_OFF + 4)

// ---------------- init ----------------
__global__ void k_init() {             // 1 block, 1024 threads
    int t = threadIdx.x;
    if (t < CH) { g_sum[t] = 0.0f; g_sumsq[t] = 0.0f; }
    if (t == 0) g_edges = 0u;
    g_cellcnt[t] = 0;
    g_cellcnt[t + 1024] = 0;
}

// decode batch element robustly (int32 / int64 / float32-converted)
__device__ __forceinline__ int decode_batch(const int* braw, int i) {
    int last = braw[NPTS - 1];
    int b;
    if (last == 0) {
        b = braw[2 * i];                   // int64 little-endian, low words
    } else if (last >= 1 && last <= 8) {
        b = braw[i];                       // int32
    } else {
        b = (int)__int_as_float(braw[i]);  // stored as float
    }
    if (b < 0) b = 0;
    if (b > 3) b = 3;
    return b;
}

// ---------------- prep: batch decode, packed pos, pos4, cell binning ----------------
__global__ void k_prep(const float* __restrict__ pos,
                       const float* __restrict__ refl,
                       const float* __restrict__ sf,
                       const int*   __restrict__ braw) {
    int i = blockIdx.x * blockDim.x + threadIdx.x;
    if (i >= NPTS) return;
    int b = decode_batch(braw, i);
    g_batch[i] = b;
    float x = pos[3 * i + 0];
    float y = pos[3 * i + 1];
    float z = pos[3 * i + 2];
    float sq = fmaf(x, x, fmaf(y, y, z * z));
    g_p4s[i] = make_float4(x, y, z, sq);
    float sc = sf[b];
    g_pos4[4 * i + 0] = x / sc;
    g_pos4[4 * i + 1] = y / sc;
    g_pos4[4 * i + 2] = z / sc;
    g_pos4[4 * i + 3] = refl[i];
    // cell binning
    int cx = (int)(x * INV_CS); cx = cx < 0 ? 0 : (cx > NC1 - 1 ? NC1 - 1 : cx);
    int cy = (int)(y * INV_CS); cy = cy < 0 ? 0 : (cy > NC1 - 1 ? NC1 - 1 : cy);
    int cz = (int)(z * INV_CS); cz = cz < 0 ? 0 : (cz > NC1 - 1 ? NC1 - 1 : cz);
    int cell = (((b * NC1 + cz) * NC1 + cy) * NC1) + cx;
    g_ptcell[i] = cell;
    g_ptslot[i] = atomicAdd(&g_cellcnt[cell], 1);
}

// ---------------- exclusive scan over 2048 cell counts (1 block, 1024 thr) ----------------
__global__ void k_scan() {
    __shared__ int s[1024];
    int t = threadIdx.x;
    int a = g_cellcnt[2 * t];
    int b = g_cellcnt[2 * t + 1];
    int pairsum = a + b;
    s[t] = pairsum;
    __syncthreads();
    for (int off = 1; off < 1024; off <<= 1) {
        int v = (t >= off) ? s[t - off] : 0;
        __syncthreads();
        s[t] += v;
        __syncthreads();
    }
    int excl = s[t] - pairsum;
    g_cellstart[2 * t]     = excl;
    g_cellstart[2 * t + 1] = excl + a;
    if (t == 1023) g_cellstart[2048] = s[1023];
}

__global__ void k_scatter() {
    int i = blockIdx.x * blockDim.x + threadIdx.x;
    if (i >= NPTS) return;
    g_perm[g_cellstart[g_ptcell[i]] + g_ptslot[i]] = i;
}

// ---------------- neighbor search via cell list ----------------
__global__ void __launch_bounds__(32) k_nbr() {
    int i = blockIdx.x * 32 + threadIdx.x;
    const float RR = (float)((0.02 * 2.1) * (0.02 * 2.1));
    float4 me = g_p4s[i];
    int b = g_batch[i];
    int cx = (int)(me.x * INV_CS); cx = cx < 0 ? 0 : (cx > NC1 - 1 ? NC1 - 1 : cx);
    int cy = (int)(me.y * INV_CS); cy = cy < 0 ? 0 : (cy > NC1 - 1 ? NC1 - 1 : cy);
    int cz = (int)(me.z * INV_CS); cz = cz < 0 ? 0 : (cz > NC1 - 1 ? NC1 - 1 : cz);
    int x0 = cx > 0 ? cx - 1 : 0;
    int x1 = cx < NC1 - 1 ? cx + 1 : NC1 - 1;
    int cnt = 0;
    int base = i * KNB;
    for (int z = (cz > 0 ? cz - 1 : 0); z <= (cz < NC1 - 1 ? cz + 1 : NC1 - 1); z++) {
        for (int y = (cy > 0 ? cy - 1 : 0); y <= (cy < NC1 - 1 ? cy + 1 : NC1 - 1); y++) {
            int crow = ((b * NC1 + z) * NC1 + y) * NC1;
            int t0 = g_cellstart[crow + x0];
            int t1 = g_cellstart[crow + x1 + 1];
            for (int t = t0; t < t1; t++) {
                int j = g_perm[t];
                float4 c = g_p4s[j];
                float dot = fmaf(me.x, c.x, fmaf(me.y, c.y, me.z * c.z));
                float d2  = (me.w + c.w) - 2.0f * dot;
                if (d2 < RR) {
                    if (cnt < KNB) {
                        g_nbr[base + cnt]   = j;
                        g_nbrd2[base + cnt] = d2;
                        cnt++;
                    } else {
                        // replace lexicographically-largest (d2, idx); matches stable top_k
                        int   mxs = 0;
                        float mxd = g_nbrd2[base];
                        int   mxi = g_nbr[base];
                        for (int s = 1; s < KNB; s++) {
                            float d  = g_nbrd2[base + s];
                            int   id = g_nbr[base + s];
                            if (d > mxd || (d == mxd && id > mxi)) { mxd = d; mxi = id; mxs = s; }
                        }
                        if (d2 < mxd || (d2 == mxd && j < mxi)) {
                            g_nbr[base + mxs]   = j;
                            g_nbrd2[base + mxs] = d2;
                        }
                    }
                }
            }
        }
    }
    g_cnt[i] = cnt;
    atomicAdd(&g_edges, (unsigned int)cnt);
}

// ---------------- edge MLP + sum accumulation (4 points per 256-thread block) ----------------
#define GBAR(g) asm volatile("bar.sync %0, 64;" :: "r"((g) + 1) : "memory")

__global__ void __launch_bounds__(256) k_mlp(const float* __restrict__ x,
                                             const float* __restrict__ w1,
                                             const float* __restrict__ b1,
                                             const float* __restrict__ w2,
                                             const float* __restrict__ b2) {
    int g = threadIdx.x >> 6;          // point group 0..3
    int c = threadIdx.x & 63;          // channel
    int i = blockIdx.x * 4 + g;
    __shared__ float featsm[4][8];
    __shared__ float h1sm[4][CH];

    int cnt = g_cnt[i];

    float w1c[8];
#pragma unroll
    for (int f = 0; f < 8; f++) w1c[f] = w1[f * CH + c];
    float w2c[CH];
#pragma unroll
    for (int f = 0; f < CH; f++) w2c[f] = w2[f * CH + c];
    float b1c = b1[c];
    float b2c = b2[c];

    float p4i0 = g_pos4[4 * i + 0];
    float p4i1 = g_pos4[4 * i + 1];
    float p4i2 = g_pos4[4 * i + 2];
    float p4i3 = g_pos4[4 * i + 3];

    float acc = 0.0f;
    for (int k = 0; k < cnt; k++) {
        int j = g_nbr[i * KNB + k];
        if (c < 4) {
            featsm[g][c] = x[j * 4 + c];
        } else if (c < 8) {
            int f = c - 4;
            float pi = (f == 0) ? p4i0 : (f == 1) ? p4i1 : (f == 2) ? p4i2 : p4i3;
            featsm[g][c] = g_pos4[j * 4 + f] - pi;
        }
        GBAR(g);
        float h = b1c;
#pragma unroll
        for (int f = 0; f < 8; f++) h = fmaf(featsm[g][f], w1c[f], h);
        h = (h >= 0.0f) ? h : 0.01f * h;
        h1sm[g][c] = h;
        GBAR(g);
        float h2 = b2c;
#pragma unroll
        for (int f = 0; f < CH; f++) h2 = fmaf(h1sm[g][f], w2c[f], h2);
        h2 = (h2 >= 0.0f) ? h2 : 0.01f * h2;
        g_h[(i * KNB + k) * CH + c] = h2;
        acc += h2;
        GBAR(g);
    }
    if (cnt > 0) atomicAdd(&g_sum[c], acc);
}

// ---------------- mean ----------------
__global__ void k_mean() {
    int c = threadIdx.x;
    if (c < CH) g_mean[c] = g_sum[c] / (float)g_edges;
}

// ---------------- sum of squared deviations ----------------
__global__ void k_sumsq() {
    int t = threadIdx.x;
    int c = t & 63;
    int r = t >> 6;          // 0..3
    float mean = g_mean[c];
    float acc = 0.0f;
    int base = blockIdx.x * 32;
    for (int pi = 0; pi < 32; pi++) {
        int i = base + pi;
        int cnt = g_cnt[i];
        for (int k = r; k < cnt; k += 4) {
            float v = g_h[(i * KNB + k) * CH + c] - mean;
            acc = fmaf(v, v, acc);
        }
    }
    __shared__ float red[256];
    red[t] = acc;
    __syncthreads();
    if (r == 0) {
        float s = red[c] + red[64 + c] + red[128 + c] + red[192 + c];
        atomicAdd(&g_sumsq[c], s);
    }
}

// ---------------- affine coefficients ----------------
__global__ void k_ab(const float* __restrict__ gamma,
                     const float* __restrict__ beta) {
    int c = threadIdx.x;
    if (c < CH) {
        float var = g_sumsq[c] / (float)g_edges;
        float inv = 1.0f / sqrtf(var + 1e-5f);
        float A = gamma[c] * inv;
        g_A[c]  = A;
        g_Bc[c] = beta[c] - g_mean[c] * A;
    }
}

// ---------------- normalize + max-aggregate (4 points per block) ----------------
__global__ void __launch_bounds__(256) k_out(float* __restrict__ out) {
    int g = threadIdx.x >> 6;
    int c = threadIdx.x & 63;
    int i = blockIdx.x * 4 + g;
    int cnt = g_cnt[i];
    float A = g_A[c], B = g_Bc[c];
    float m = NEGV;
    for (int k = 0; k < cnt; k++) {
        float v = fmaf(g_h[(i * KNB + k) * CH + c], A, B);
        m = fmaxf(m, v);
    }
    out[i * CH + c] = m;
}

// ---------------- tuple passthrough ----------------
__global__ void k_pass(float* __restrict__ out,
                       const float* __restrict__ pos,
                       const float* __restrict__ refl,
                       const float* __restrict__ sf) {
    int idx = blockIdx.x * blockDim.x + threadIdx.x;
    if (idx < 3 * NPTS) {
        out[POS_OFF + idx] = pos[idx];
    } else if (idx < 4 * NPTS) {
        int j = idx - 3 * NPTS;
        out[BATCH_OFF + j] = (float)g_batch[j];
    } else if (idx < 5 * NPTS) {
        int j = idx - 4 * NPTS;
        out[REF_OFF + j] = refl[j];
    } else if (idx < 5 * NPTS + 4) {
        int j = idx - 5 * NPTS;
        out[SF_OFF + j] = sf[j];
    }
}

extern "C" void kernel_launch(void* const* d_in, const int* in_sizes, int n_in,
                              void* d_out, int out_size) {
    const float* x     = (const float*)d_in[0];
    const float* pos   = (const float*)d_in[1];
    const float* refl  = (const float*)d_in[2];
    const float* sf    = (const float*)d_in[3];
    const float* w1    = (const float*)d_in[4];
    const float* b1    = (const float*)d_in[5];
    const float* w2    = (const float*)d_in[6];
    const float* b2    = (const float*)d_in[7];
    const float* gamma = (const float*)d_in[8];
    const float* beta  = (const float*)d_in[9];
    const int*   braw  = (const int*)d_in[10];
    float* out = (float*)d_out;

    k_init<<<1, 1024>>>();
    k_prep<<<NPTS / 256, 256>>>(pos, refl, sf, braw);
    k_scan<<<1, 1024>>>();
    k_scatter<<<NPTS / 256, 256>>>();
    k_nbr<<<NPTS / 32, 32>>>();
    k_mlp<<<NPTS / 4, 256>>>(x, w1, b1, w2, b2);
    k_mean<<<1, 64>>>();
    k_sumsq<<<NPTS / 32, 256>>>();
    k_ab<<<1, 64>>>(gamma, beta);
    k_out<<<NPTS / 4, 256>>>(out);
    if (out_size >= TOTAL_OUT) {
        k_pass<<<(5 * NPTS + 4 + 255) / 256, 256>>>(out, pos, refl, sf);
    }
}

// round 10
// speedup vs baseline: 2.1056x; 1.1248x over previous
#include <cuda_runtime.h>
#include <math.h>

#define NPTS 8192
#define KNB  32
#define CH   64
#define NEGV (-1e30f)

#define NC1     8                       // cells per dim
#define NCELLS  (4 * NC1 * NC1 * NC1)   // 2048 (4 batches)
#define INV_CS  20.0f                   // 1 / 0.05 ; 0.05 > R = 0.042

// ---------------- scratch (device globals; no allocation) ----------------
static __device__ float4 g_p4s[NPTS];          // (x, y, z, |p|^2) unscaled
static __device__ float  g_pos4[NPTS * 4];     // (x/s, y/s, z/s, refl)
static __device__ int    g_batch[NPTS];
static __device__ int    g_nbr[NPTS * KNB];
static __device__ float  g_nbrd2[NPTS * KNB];
static __device__ int    g_cnt[NPTS];
static __device__ float  g_h[NPTS * KNB * CH]; // 64 MB scratch (valid slots only)
static __device__ float  g_sum[CH];            // zeroed by cleanup / .bss
static __device__ float  g_sumsq[CH];
static __device__ int    g_ealloc;             // edge counter (cleanup-zeroed)
static __device__ int    g_epack[NPTS * KNB];  // flattened edges: i*KNB+k
// cell-list structures
static __device__ int    g_cellcnt[NCELLS];    // cleanup-zeroed
static __device__ int    g_cellstart[NCELLS + 1];
static __device__ int    g_ptcell[NPTS];
static __device__ int    g_ptslot[NPTS];
static __device__ float4 g_ps_sorted[NPTS];    // positions in cell order
static __device__ int    g_sortidx[NPTS];      // sorted slot -> original index

// output layout: out[N,64] | pos[N,3] | batch[N] | reflectance[N] | sf[4]
#define POS_OFF   (NPTS * CH)
#define BATCH_OFF (POS_OFF + NPTS * 3)
#define REF_OFF   (BATCH_OFF + NPTS)
#define SF_OFF    (REF_OFF + NPTS)
#define TOTAL_OUT (SF_OFF + 4)

// decode batch element robustly (int32 / int64 / float32-converted)
__device__ __forceinline__ int decode_batch(const int* braw, int i) {
    int last = braw[NPTS - 1];
    int b;
    if (last == 0) {
        b = braw[2 * i];                   // int64 little-endian, low words
    } else if (last >= 1 && last <= 8) {
        b = braw[i];                       // int32
    } else {
        b = (int)__int_as_float(braw[i]);  // stored as float
    }
    if (b < 0) b = 0;
    if (b > 3) b = 3;
    return b;
}

// ---------------- prep: batch decode, packed pos, pos4, cell binning ----------------
// relies on g_cellcnt == 0 on entry (initial .bss zero; re-zeroed by k_pass cleanup)
__global__ void k_prep(const float* __restrict__ pos,
                       const float* __restrict__ refl,
                       const float* __restrict__ sf,
                       const int*   __restrict__ braw) {
    int i = blockIdx.x * blockDim.x + threadIdx.x;
    if (i >= NPTS) return;
    int b = decode_batch(braw, i);
    g_batch[i] = b;
    float x = pos[3 * i + 0];
    float y = pos[3 * i + 1];
    float z = pos[3 * i + 2];
    float sq = fmaf(x, x, fmaf(y, y, z * z));
    g_p4s[i] = make_float4(x, y, z, sq);
    float sc = sf[b];
    g_pos4[4 * i + 0] = x / sc;
    g_pos4[4 * i + 1] = y / sc;
    g_pos4[4 * i + 2] = z / sc;
    g_pos4[4 * i + 3] = refl[i];
    // cell binning
    int cx = (int)(x * INV_CS); cx = cx < 0 ? 0 : (cx > NC1 - 1 ? NC1 - 1 : cx);
    int cy = (int)(y * INV_CS); cy = cy < 0 ? 0 : (cy > NC1 - 1 ? NC1 - 1 : cy);
    int cz = (int)(z * INV_CS); cz = cz < 0 ? 0 : (cz > NC1 - 1 ? NC1 - 1 : cz);
    int cell = (((b * NC1 + cz) * NC1 + cy) * NC1) + cx;
    g_ptcell[i] = cell;
    g_ptslot[i] = atomicAdd(&g_cellcnt[cell], 1);
}

// ---------------- exclusive scan over 2048 cell counts (1 block, 1024 thr) ----------------
__global__ void k_scan() {
    __shared__ int s[1024];
    int t = threadIdx.x;
    int a = g_cellcnt[2 * t];
    int b = g_cellcnt[2 * t + 1];
    int pairsum = a + b;
    s[t] = pairsum;
    __syncthreads();
    for (int off = 1; off < 1024; off <<= 1) {
        int v = (t >= off) ? s[t - off] : 0;
        __syncthreads();
        s[t] += v;
        __syncthreads();
    }
    int excl = s[t] - pairsum;
    g_cellstart[2 * t]     = excl;
    g_cellstart[2 * t + 1] = excl + a;
    if (t == 1023) g_cellstart[2048] = s[1023];
}

// ---------------- scatter: positions into cell order (no indirection later) ----------------
__global__ void k_scatter() {
    int i = blockIdx.x * blockDim.x + threadIdx.x;
    if (i >= NPTS) return;
    int t = g_cellstart[g_ptcell[i]] + g_ptslot[i];
    g_ps_sorted[t] = g_p4s[i];
    g_sortidx[t]   = i;
}

// ---------------- neighbor search via cell list (streaming sorted candidates) ----------------
__global__ void __launch_bounds__(32) k_nbr() {
    int i = blockIdx.x * 32 + threadIdx.x;
    const float RR = (float)((0.02 * 2.1) * (0.02 * 2.1));
    float4 me = g_p4s[i];
    int b = g_batch[i];
    int cx = (int)(me.x * INV_CS); cx = cx < 0 ? 0 : (cx > NC1 - 1 ? NC1 - 1 : cx);
    int cy = (int)(me.y * INV_CS); cy = cy < 0 ? 0 : (cy > NC1 - 1 ? NC1 - 1 : cy);
    int cz = (int)(me.z * INV_CS); cz = cz < 0 ? 0 : (cz > NC1 - 1 ? NC1 - 1 : cz);
    int x0 = cx > 0 ? cx - 1 : 0;
    int x1 = cx < NC1 - 1 ? cx + 1 : NC1 - 1;
    int cnt = 0;
    int base = i * KNB;
    for (int z = (cz > 0 ? cz - 1 : 0); z <= (cz < NC1 - 1 ? cz + 1 : NC1 - 1); z++) {
        for (int y = (cy > 0 ? cy - 1 : 0); y <= (cy < NC1 - 1 ? cy + 1 : NC1 - 1); y++) {
            int crow = ((b * NC1 + z) * NC1 + y) * NC1;
            int t0 = g_cellstart[crow + x0];
            int t1 = g_cellstart[crow + x1 + 1];
            for (int t = t0; t < t1; t++) {
                float4 c = g_ps_sorted[t];
                float dot = fmaf(me.x, c.x, fmaf(me.y, c.y, me.z * c.z));
                float d2  = (me.w + c.w) - 2.0f * dot;
                if (d2 < RR) {
                    int j = g_sortidx[t];
                    if (cnt < KNB) {
                        g_nbr[base + cnt]   = j;
                        g_nbrd2[base + cnt] = d2;
                        cnt++;
                    } else {
                        // replace lexicographically-largest (d2, idx); matches stable top_k
                        int   mxs = 0;
                        float mxd = g_nbrd2[base];
                        int   mxi = g_nbr[base];
                        for (int s = 1; s < KNB; s++) {
                            float d  = g_nbrd2[base + s];
                            int   id = g_nbr[base + s];
                            if (d > mxd || (d == mxd && id > mxi)) { mxd = d; mxi = id; mxs = s; }
                        }
                        if (d2 < mxd || (d2 == mxd && j < mxi)) {
                            g_nbr[base + mxs]   = j;
                            g_nbrd2[base + mxs] = d2;
                        }
                    }
                }
            }
        }
    }
    g_cnt[i] = cnt;
    // append to flattened edge list
    int off = atomicAdd(&g_ealloc, cnt);
    for (int k = 0; k < cnt; k++) g_epack[off + k] = base + k;
}

// ---------------- edge-parallel MLP: 16 edges per 256-thread block ----------------
#define EDGES_PER_BLK 16
__global__ void __launch_bounds__(256) k_mlp(const float* __restrict__ x,
                                             const float* __restrict__ w1,
                                             const float* __restrict__ b1,
                                             const float* __restrict__ w2,
                                             const float* __restrict__ b2) {
    int E  = g_ealloc;
    int e0 = blockIdx.x * EDGES_PER_BLK;
    if (e0 >= E) return;
    int slot = threadIdx.x >> 6;       // 0..3
    int c    = threadIdx.x & 63;       // channel
    __shared__ float featsm[4][8];
    __shared__ float h1sm[4][CH];
    __shared__ float redsm[4][CH];

    float w1c[8];
#pragma unroll
    for (int f = 0; f < 8; f++) w1c[f] = w1[f * CH + c];
    float w2c[CH];
#pragma unroll
    for (int f = 0; f < CH; f++) w2c[f] = w2[f * CH + c];
    float b1c = b1[c];
    float b2c = b2[c];

    float acc = 0.0f;
#pragma unroll
    for (int it = 0; it < EDGES_PER_BLK / 4; it++) {
        int e = e0 + it * 4 + slot;
        bool act = (e < E);
        int pk = 0, i = 0, j = 0;
        if (act) {
            pk = g_epack[e];
            i  = pk >> 5;              // KNB = 32
            j  = g_nbr[pk];
        }
        if (act && c < 8) {
            if (c < 4) {
                featsm[slot][c] = x[j * 4 + c];
            } else {
                int f = c - 4;
                featsm[slot][c] = g_pos4[j * 4 + f] - g_pos4[i * 4 + f];
            }
        }
        __syncthreads();
        float h = b1c;
#pragma unroll
        for (int f = 0; f < 8; f++) h = fmaf(featsm[slot][f], w1c[f], h);
        h = (h >= 0.0f) ? h : 0.01f * h;
        h1sm[slot][c] = h;
        __syncthreads();
        float h2 = b2c;
#pragma unroll
        for (int f = 0; f < CH; f++) h2 = fmaf(h1sm[slot][f], w2c[f], h2);
        h2 = (h2 >= 0.0f) ? h2 : 0.01f * h2;
        if (act) {
            g_h[pk * CH + c] = h2;
            acc += h2;
        }
        __syncthreads();
    }
    redsm[slot][c] = acc;
    __syncthreads();
    if (slot == 0) {
        float s = redsm[0][c] + redsm[1][c] + redsm[2][c] + redsm[3][c];
        atomicAdd(&g_sum[c], s);
    }
}

// ---------------- sum of squared deviations (mean computed inline) ----------------
__global__ void k_sumsq() {
    int t = threadIdx.x;
    int c = t & 63;
    int r = t >> 6;          // 0..3
    float mean = g_sum[c] / (float)g_ealloc;
    float acc = 0.0f;
    int base = blockIdx.x * 32;
    for (int pi = 0; pi < 32; pi++) {
        int i = base + pi;
        int cnt = g_cnt[i];
        for (int k = r; k < cnt; k += 4) {
            float v = g_h[(i * KNB + k) * CH + c] - mean;
            acc = fmaf(v, v, acc);
        }
    }
    __shared__ float red[256];
    red[t] = acc;
    __syncthreads();
    if (r == 0) {
        float s = red[c] + red[64 + c] + red[128 + c] + red[192 + c];
        atomicAdd(&g_sumsq[c], s);
    }
}

// ---------------- normalize + max-aggregate (affine computed inline) ----------------
__global__ void __launch_bounds__(256) k_out(float* __restrict__ out,
                                             const float* __restrict__ gamma,
                                             const float* __restrict__ beta) {
    int g = threadIdx.x >> 6;
    int c = threadIdx.x & 63;
    int i = blockIdx.x * 4 + g;
    int cnt = g_cnt[i];
    float invE = 1.0f / (float)g_ealloc;
    float mean = g_sum[c] * invE;
    float var  = g_sumsq[c] * invE;
    float A = gamma[c] * (1.0f / sqrtf(var + 1e-5f));
    float B = beta[c] - mean * A;
    float m = NEGV;
    for (int k = 0; k < cnt; k++) {
        float v = fmaf(g_h[(i * KNB + k) * CH + c], A, B);
        m = fmaxf(m, v);
    }
    out[i * CH + c] = m;
}

// ---------------- tuple passthrough + state cleanup for next call ----------------
__global__ void k_pass(float* __restrict__ out,
                       const float* __restrict__ pos,
                       const float* __restrict__ refl,
                       const float* __restrict__ sf,
                       int do_pass) {
    int idx = blockIdx.x * blockDim.x + threadIdx.x;
    // cleanup (restores the zeroed-state invariant this call consumed)
    if (idx < NCELLS) g_cellcnt[idx] = 0;
    if (idx < CH) { g_sum[idx] = 0.0f; g_sumsq[idx] = 0.0f; }
    if (idx == 0) g_ealloc = 0;
    if (!do_pass) return;
    if (idx < 3 * NPTS) {
        out[POS_OFF + idx] = pos[idx];
    } else if (idx < 4 * NPTS) {
        int j = idx - 3 * NPTS;
        out[BATCH_OFF + j] = (float)g_batch[j];
    } else if (idx < 5 * NPTS) {
        int j = idx - 4 * NPTS;
        out[REF_OFF + j] = refl[j];
    } else if (idx < 5 * NPTS + 4) {
        int j = idx - 5 * NPTS;
        out[SF_OFF + j] = sf[j];
    }
}

extern "C" void kernel_launch(void* const* d_in, const int* in_sizes, int n_in,
                              void* d_out, int out_size) {
    const float* x     = (const float*)d_in[0];
    const float* pos   = (const float*)d_in[1];
    const float* refl  = (const float*)d_in[2];
    const float* sf    = (const float*)d_in[3];
    const float* w1    = (const float*)d_in[4];
    const float* b1    = (const float*)d_in[5];
    const float* w2    = (const float*)d_in[6];
    const float* b2    = (const float*)d_in[7];
    const float* gamma = (const float*)d_in[8];
    const float* beta  = (const float*)d_in[9];
    const int*   braw  = (const int*)d_in[10];
    float* out = (float*)d_out;

    k_prep<<<NPTS / 256, 256>>>(pos, refl, sf, braw);
    k_scan<<<1, 1024>>>();
    k_scatter<<<NPTS / 256, 256>>>();
    k_nbr<<<NPTS / 32, 32>>>();
    k_mlp<<<NPTS * KNB / EDGES_PER_BLK, 256>>>(x, w1, b1, w2, b2);
    k_sumsq<<<NPTS / 32, 256>>>();
    k_out<<<NPTS / 4, 256>>>(out, gamma, beta);
    int do_pass = (out_size >= TOTAL_OUT) ? 1 : 0;
    k_pass<<<(5 * NPTS + 4 + 255) / 256, 256>>>(out, pos, refl, sf, do_pass);
}

// round 11
// speedup vs baseline: 3.4130x; 1.6209x over previous
#include <cuda_runtime.h>
#include <math.h>

#define NPTS 8192
#define KNB  32
#define CH   64
#define NEGV (-1e30f)

#define NC1     8                       // cells per dim
#define NCELLS  (4 * NC1 * NC1 * NC1)   // 2048 (4 batches)
#define INV_CS  20.0f                   // 1 / 0.05 ; 0.05 > R = 0.042

// ---------------- scratch (device globals; no allocation) ----------------
static __device__ float4 g_p4s[NPTS];          // (x, y, z, |p|^2) unscaled
static __device__ float  g_pos4[NPTS * 4];     // (x/s, y/s, z/s, refl)
static __device__ int    g_batch[NPTS];
static __device__ int    g_nbr[NPTS * KNB];
static __device__ float  g_nbrd2[NPTS * KNB];
static __device__ int    g_cnt[NPTS];
static __device__ float  g_sum[CH];            // zeroed by cleanup / .bss
static __device__ float  g_sumsq[CH];
static __device__ unsigned g_maxord[NPTS * CH];// ordered-uint max(h); self-cleaned in k_out
static __device__ int    g_ealloc;             // edge counter (cleanup-zeroed)
static __device__ int    g_epack[NPTS * KNB];  // flattened edges: i*KNB+k
// cell-list structures
static __device__ int    g_cellcnt[NCELLS];    // cleanup-zeroed
static __device__ int    g_cellstart[NCELLS + 1];
static __device__ int    g_ptcell[NPTS];
static __device__ int    g_ptslot[NPTS];
static __device__ float4 g_ps_sorted[NPTS];    // positions in cell order
static __device__ int    g_sortidx[NPTS];      // sorted slot -> original index

// output layout: out[N,64] | pos[N,3] | batch[N] | reflectance[N] | sf[4]
#define POS_OFF   (NPTS * CH)
#define BATCH_OFF (POS_OFF + NPTS * 3)
#define REF_OFF   (BATCH_OFF + NPTS)
#define SF_OFF    (REF_OFF + NPTS)
#define TOTAL_OUT (SF_OFF + 4)

// monotone float <-> ordered-uint (0 == "below -inf" sentinel)
__device__ __forceinline__ unsigned ford(float f) {
    unsigned u = __float_as_uint(f);
    return (u & 0x80000000u) ? ~u : (u | 0x80000000u);
}
__device__ __forceinline__ float dord(unsigned u) {
    return __uint_as_float((u & 0x80000000u) ? (u & 0x7FFFFFFFu) : ~u);
}

// decode batch element robustly (int32 / int64 / float32-converted)
__device__ __forceinline__ int decode_batch(const int* braw, int i) {
    int last = braw[NPTS - 1];
    int b;
    if (last == 0) {
        b = braw[2 * i];                   // int64 little-endian, low words
    } else if (last >= 1 && last <= 8) {
        b = braw[i];                       // int32
    } else {
        b = (int)__int_as_float(braw[i]);  // stored as float
    }
    if (b < 0) b = 0;
    if (b > 3) b = 3;
    return b;
}

// ---------------- prep: batch decode, packed pos, pos4, cell binning ----------------
// relies on g_cellcnt == 0 on entry (initial .bss zero; re-zeroed by k_pass cleanup)
__global__ void k_prep(const float* __restrict__ pos,
                       const float* __restrict__ refl,
                       const float* __restrict__ sf,
                       const int*   __restrict__ braw) {
    int i = blockIdx.x * blockDim.x + threadIdx.x;
    if (i >= NPTS) return;
    int b = decode_batch(braw, i);
    g_batch[i] = b;
    float x = pos[3 * i + 0];
    float y = pos[3 * i + 1];
    float z = pos[3 * i + 2];
    float sq = fmaf(x, x, fmaf(y, y, z * z));
    g_p4s[i] = make_float4(x, y, z, sq);
    float sc = sf[b];
    g_pos4[4 * i + 0] = x / sc;
    g_pos4[4 * i + 1] = y / sc;
    g_pos4[4 * i + 2] = z / sc;
    g_pos4[4 * i + 3] = refl[i];
    // cell binning
    int cx = (int)(x * INV_CS); cx = cx < 0 ? 0 : (cx > NC1 - 1 ? NC1 - 1 : cx);
    int cy = (int)(y * INV_CS); cy = cy < 0 ? 0 : (cy > NC1 - 1 ? NC1 - 1 : cy);
    int cz = (int)(z * INV_CS); cz = cz < 0 ? 0 : (cz > NC1 - 1 ? NC1 - 1 : cz);
    int cell = (((b * NC1 + cz) * NC1 + cy) * NC1) + cx;
    g_ptcell[i] = cell;
    g_ptslot[i] = atomicAdd(&g_cellcnt[cell], 1);
}

// ---------------- exclusive scan over 2048 cell counts (1 block, 1024 thr) ----------------
__global__ void k_scan() {
    __shared__ int s[1024];
    int t = threadIdx.x;
    int a = g_cellcnt[2 * t];
    int b = g_cellcnt[2 * t + 1];
    int pairsum = a + b;
    s[t] = pairsum;
    __syncthreads();
    for (int off = 1; off < 1024; off <<= 1) {
        int v = (t >= off) ? s[t - off] : 0;
        __syncthreads();
        s[t] += v;
        __syncthreads();
    }
    int excl = s[t] - pairsum;
    g_cellstart[2 * t]     = excl;
    g_cellstart[2 * t + 1] = excl + a;
    if (t == 1023) g_cellstart[2048] = s[1023];
}

// ---------------- scatter: positions into cell order ----------------
__global__ void k_scatter() {
    int i = blockIdx.x * blockDim.x + threadIdx.x;
    if (i >= NPTS) return;
    int t = g_cellstart[g_ptcell[i]] + g_ptslot[i];
    g_ps_sorted[t] = g_p4s[i];
    g_sortidx[t]   = i;
}

// ---------------- neighbor search: one WARP per point ----------------
// Lanes scan candidate spans in parallel; ballot+prefix preserves exact
// t-ascending insertion order (identical list to the serial version).
__global__ void __launch_bounds__(256) k_nbr() {
    const unsigned FULL = 0xFFFFFFFFu;
    int lane = threadIdx.x & 31;
    int i = blockIdx.x * 8 + (threadIdx.x >> 5);
    const float RR = (float)((0.02 * 2.1) * (0.02 * 2.1));
    float4 me = g_p4s[i];
    int b = g_batch[i];
    int cx = (int)(me.x * INV_CS); cx = cx < 0 ? 0 : (cx > NC1 - 1 ? NC1 - 1 : cx);
    int cy = (int)(me.y * INV_CS); cy = cy < 0 ? 0 : (cy > NC1 - 1 ? NC1 - 1 : cy);
    int cz = (int)(me.z * INV_CS); cz = cz < 0 ? 0 : (cz > NC1 - 1 ? NC1 - 1 : cz);
    int x0 = cx > 0 ? cx - 1 : 0;
    int x1 = cx < NC1 - 1 ? cx + 1 : NC1 - 1;
    int z0 = cz > 0 ? cz - 1 : 0, z1 = cz < NC1 - 1 ? cz + 1 : NC1 - 1;
    int y0 = cy > 0 ? cy - 1 : 0, y1 = cy < NC1 - 1 ? cy + 1 : NC1 - 1;
    int cnt = 0;
    int base = i * KNB;
    for (int z = z0; z <= z1; z++) {
        for (int y = y0; y <= y1; y++) {
            int crow = ((b * NC1 + z) * NC1 + y) * NC1;
            int t0 = g_cellstart[crow + x0];
            int t1 = g_cellstart[crow + x1 + 1];
            for (int tb = t0; tb < t1; tb += 32) {
                int t = tb + lane;
                bool hit = false; float d2 = 0.0f; int j = -1;
                if (t < t1) {
                    float4 c = g_ps_sorted[t];
                    float dot = fmaf(me.x, c.x, fmaf(me.y, c.y, me.z * c.z));
                    d2 = (me.w + c.w) - 2.0f * dot;
                    if (d2 < RR) { hit = true; j = g_sortidx[t]; }
                }
                unsigned mask = __ballot_sync(FULL, hit);
                int pos = cnt + __popc(mask & ((1u << lane) - 1u));
                if (hit && pos < KNB) {
                    g_nbr[base + pos]   = j;
                    g_nbrd2[base + pos] = d2;
                }
                int newcnt = cnt + __popc(mask);
                if (newcnt > KNB) {
                    // rare overflow: serial lex-(d2,idx) replacement, t-ascending
                    __syncwarp(FULL);
                    unsigned of = __ballot_sync(FULL, hit && pos >= KNB);
                    while (of) {
                        int src = __ffs(of) - 1;
                        float dd = __shfl_sync(FULL, d2, src);
                        int   jj = __shfl_sync(FULL, j, src);
                        if (lane == 0) {
                            int mxs = 0; float mxd = g_nbrd2[base]; int mxi = g_nbr[base];
                            for (int s = 1; s < KNB; s++) {
                                float d = g_nbrd2[base + s]; int id = g_nbr[base + s];
                                if (d > mxd || (d == mxd && id > mxi)) { mxd = d; mxi = id; mxs = s; }
                            }
                            if (dd < mxd || (dd == mxd && jj < mxi)) {
                                g_nbr[base + mxs] = jj; g_nbrd2[base + mxs] = dd;
                            }
                        }
                        __syncwarp(FULL);
                        of &= of - 1;
                    }
                    cnt = KNB;
                } else {
                    cnt = newcnt;
                }
            }
        }
    }
    int off = 0;
    if (lane == 0) {
        g_cnt[i] = cnt;
        off = atomicAdd(&g_ealloc, cnt);
    }
    off = __shfl_sync(FULL, off, 0);
    if (lane < cnt) g_epack[off + lane] = base + lane;
}

// ---------------- edge-parallel MLP: sums + sumsq + per-point max, no h store ----
#define EDGES_PER_BLK 16
__global__ void __launch_bounds__(256) k_mlp(const float* __restrict__ x,
                                             const float* __restrict__ w1,
                                             const float* __restrict__ b1,
                                             const float* __restrict__ w2,
                                             const float* __restrict__ b2) {
    int E  = g_ealloc;
    int e0 = blockIdx.x * EDGES_PER_BLK;
    if (e0 >= E) return;
    int slot = threadIdx.x >> 6;       // 0..3
    int c    = threadIdx.x & 63;       // channel
    __shared__ float featsm[4][8];
    __shared__ float h1sm[4][CH];
    __shared__ float redsm[4][CH];
    __shared__ float redsm2[4][CH];

    float w1c[8];
#pragma unroll
    for (int f = 0; f < 8; f++) w1c[f] = w1[f * CH + c];
    float w2c[CH];
#pragma unroll
    for (int f = 0; f < CH; f++) w2c[f] = w2[f * CH + c];
    float b1c = b1[c];
    float b2c = b2[c];

    float acc = 0.0f, acc2 = 0.0f;
    int cur_i = -1; unsigned cur_mx = 0u;
#pragma unroll
    for (int it = 0; it < EDGES_PER_BLK / 4; it++) {
        int e = e0 + slot * 4 + it;    // slot-major: this thread's edges consecutive
        bool act = (e < E);
        int pk = 0, i = 0, j = 0;
        if (act) {
            pk = g_epack[e];
            i  = pk >> 5;              // KNB = 32
            j  = g_nbr[pk];
        }
        if (act && c < 8) {
            if (c < 4) {
                featsm[slot][c] = x[j * 4 + c];
            } else {
                int f = c - 4;
                featsm[slot][c] = g_pos4[j * 4 + f] - g_pos4[i * 4 + f];
            }
        }
        __syncthreads();
        float h = b1c;
#pragma unroll
        for (int f = 0; f < 8; f++) h = fmaf(featsm[slot][f], w1c[f], h);
        h = (h >= 0.0f) ? h : 0.01f * h;
        h1sm[slot][c] = h;
        __syncthreads();
        float h2 = b2c;
#pragma unroll
        for (int f = 0; f < CH; f++) h2 = fmaf(h1sm[slot][f], w2c[f], h2);
        h2 = (h2 >= 0.0f) ? h2 : 0.01f * h2;
        if (act) {
            acc  += h2;
            acc2  = fmaf(h2, h2, acc2);
            unsigned ord = ford(h2);
            if (i != cur_i) {
                if (cur_i >= 0) atomicMax(&g_maxord[cur_i * CH + c], cur_mx);
                cur_i = i; cur_mx = ord;
            } else if (ord > cur_mx) {
                cur_mx = ord;
            }
        }
        __syncthreads();
    }
    if (cur_i >= 0) atomicMax(&g_maxord[cur_i * CH + c], cur_mx);
    redsm[slot][c]  = acc;
    redsm2[slot][c] = acc2;
    __syncthreads();
    if (slot == 0) {
        float s  = redsm[0][c]  + redsm[1][c]  + redsm[2][c]  + redsm[3][c];
        float s2 = redsm2[0][c] + redsm2[1][c] + redsm2[2][c] + redsm2[3][c];
        atomicAdd(&g_sum[c], s);
        atomicAdd(&g_sumsq[c], s2);
    }
}

// ---------------- BN affine on the pre-computed max (gamma > 0: max commutes) ----
__global__ void __launch_bounds__(256) k_out(float* __restrict__ out,
                                             const float* __restrict__ gamma,
                                             const float* __restrict__ beta) {
    int g = threadIdx.x >> 6;
    int c = threadIdx.x & 63;
    int i = blockIdx.x * 4 + g;
    int cnt = g_cnt[i];
    float invE = 1.0f / (float)g_ealloc;
    float mean = g_sum[c] * invE;
    float var  = g_sumsq[c] * invE - mean * mean;
    if (var < 0.0f) var = 0.0f;
    float A = gamma[c] * rsqrtf(var + 1e-5f);
    float B = beta[c] - mean * A;
    unsigned mo = g_maxord[i * CH + c];
    g_maxord[i * CH + c] = 0u;                 // self-clean for next call
    out[i * CH + c] = (cnt > 0) ? fmaf(dord(mo), A, B) : NEGV;
}

// ---------------- tuple passthrough + state cleanup for next call ----------------
__global__ void k_pass(float* __restrict__ out,
                       const float* __restrict__ pos,
                       const float* __restrict__ refl,
                       const float* __restrict__ sf,
                       int do_pass) {
    int idx = blockIdx.x * blockDim.x + threadIdx.x;
    // cleanup (restores the zeroed-state invariant this call consumed)
    if (idx < NCELLS) g_cellcnt[idx] = 0;
    if (idx < CH) { g_sum[idx] = 0.0f; g_sumsq[idx] = 0.0f; }
    if (idx == 0) g_ealloc = 0;
    if (!do_pass) return;
    if (idx < 3 * NPTS) {
        out[POS_OFF + idx] = pos[idx];
    } else if (idx < 4 * NPTS) {
        int j = idx - 3 * NPTS;
        out[BATCH_OFF + j] = (float)g_batch[j];
    } else if (idx < 5 * NPTS) {
        int j = idx - 4 * NPTS;
        out[REF_OFF + j] = refl[j];
    } else if (idx < 5 * NPTS + 4) {
        int j = idx - 5 * NPTS;
        out[SF_OFF + j] = sf[j];
    }
}

extern "C" void kernel_launch(void* const* d_in, const int* in_sizes, int n_in,
                              void* d_out, int out_size) {
    const float* x     = (const float*)d_in[0];
    const float* pos   = (const float*)d_in[1];
    const float* refl  = (const float*)d_in[2];
    const float* sf    = (const float*)d_in[3];
    const float* w1    = (const float*)d_in[4];
    const float* b1    = (const float*)d_in[5];
    const float* w2    = (const float*)d_in[6];
    const float* b2    = (const float*)d_in[7];
    const float* gamma = (const float*)d_in[8];
    const float* beta  = (const float*)d_in[9];
    const int*   braw  = (const int*)d_in[10];
    float* out = (float*)d_out;

    k_prep<<<NPTS / 256, 256>>>(pos, refl, sf, braw);
    k_scan<<<1, 1024>>>();
    k_scatter<<<NPTS / 256, 256>>>();
    k_nbr<<<NPTS / 8, 256>>>();
    k_mlp<<<NPTS * KNB / EDGES_PER_BLK, 256>>>(x, w1, b1, w2, b2);
    k_out<<<NPTS / 4, 256>>>(out, gamma, beta);
    int do_pass = (out_size >= TOTAL_OUT) ? 1 : 0;
    k_pass<<<(5 * NPTS + 4 + 255) / 256, 256>>>(out, pos, refl, sf, do_pass);
}

// round 12
// speedup vs baseline: 3.8991x; 1.1424x over previous
#include <cuda_runtime.h>
#include <math.h>

#define NPTS 8192
#define KNB  32
#define CH   64
#define NEGV (-1e30f)

#define NC1     8                       // cells per dim
#define NCELLS  (4 * NC1 * NC1 * NC1)   // 2048 (4 batches)
#define INV_CS  20.0f                   // 1 / 0.05 ; 0.05 > R = 0.042

// ---------------- scratch (device globals; no allocation) ----------------
static __device__ float4 g_p4s[NPTS];          // (x, y, z, |p|^2) unscaled
static __device__ float  g_pos4[NPTS * 4];     // (x/s, y/s, z/s, refl)
static __device__ int    g_batch[NPTS];
static __device__ int    g_nbr[NPTS * KNB];
static __device__ float  g_nbrd2[NPTS * KNB];
static __device__ int    g_cnt[NPTS];
static __device__ float  g_sum[CH];            // zeroed at start of call (k_prep)
static __device__ float  g_sumsq[CH];
static __device__ unsigned g_maxord[NPTS * CH];// ordered-uint max(h); self-cleaned in k_out
static __device__ int    g_ealloc;             // edge counter (zeroed in k_prep)
static __device__ int    g_epack[NPTS * KNB];  // flattened edges: i*KNB+k
// cell-list structures
static __device__ int    g_cellcnt[NCELLS];    // zeroed at END of call (k_out merge)
static __device__ int    g_cellstart[NCELLS + 1];
static __device__ int    g_ptcell[NPTS];
static __device__ int    g_ptslot[NPTS];
static __device__ float4 g_ps_sorted[NPTS];    // positions in cell order
static __device__ int    g_sortidx[NPTS];      // sorted slot -> original index

// output layout: out[N,64] | pos[N,3] | batch[N] | reflectance[N] | sf[4]
#define POS_OFF   (NPTS * CH)
#define BATCH_OFF (POS_OFF + NPTS * 3)
#define REF_OFF   (BATCH_OFF + NPTS)
#define SF_OFF    (REF_OFF + NPTS)
#define TOTAL_OUT (SF_OFF + 4)

// monotone float <-> ordered-uint (0 == "below -inf" sentinel)
__device__ __forceinline__ unsigned ford(float f) {
    unsigned u = __float_as_uint(f);
    return (u & 0x80000000u) ? ~u : (u | 0x80000000u);
}
__device__ __forceinline__ float dord(unsigned u) {
    return __uint_as_float((u & 0x80000000u) ? (u & 0x7FFFFFFFu) : ~u);
}

// decode batch element robustly (int32 / int64 / float32-converted)
__device__ __forceinline__ int decode_batch(const int* braw, int i) {
    int last = braw[NPTS - 1];
    int b;
    if (last == 0) {
        b = braw[2 * i];                   // int64 little-endian, low words
    } else if (last >= 1 && last <= 8) {
        b = braw[i];                       // int32
    } else {
        b = (int)__int_as_float(braw[i]);  // stored as float
    }
    if (b < 0) b = 0;
    if (b > 3) b = 3;
    return b;
}

// ---------------- prep: batch decode, packed pos, pos4, cell binning ----------------
// g_cellcnt == 0 on entry (.bss on call 1; re-zeroed by k_out at end of prior call).
// Also zeroes this call's accumulators (produced strictly later -> race-free).
__global__ void k_prep(const float* __restrict__ pos,
                       const float* __restrict__ refl,
                       const float* __restrict__ sf,
                       const int*   __restrict__ braw) {
    int i = blockIdx.x * blockDim.x + threadIdx.x;
    if (i < CH) { g_sum[i] = 0.0f; g_sumsq[i] = 0.0f; }
    if (i == 0) g_ealloc = 0;
    if (i >= NPTS) return;
    int b = decode_batch(braw, i);
    g_batch[i] = b;
    float x = pos[3 * i + 0];
    float y = pos[3 * i + 1];
    float z = pos[3 * i + 2];
    float sq = fmaf(x, x, fmaf(y, y, z * z));
    g_p4s[i] = make_float4(x, y, z, sq);
    float sc = sf[b];
    g_pos4[4 * i + 0] = x / sc;
    g_pos4[4 * i + 1] = y / sc;
    g_pos4[4 * i + 2] = z / sc;
    g_pos4[4 * i + 3] = refl[i];
    // cell binning
    int cx = (int)(x * INV_CS); cx = cx < 0 ? 0 : (cx > NC1 - 1 ? NC1 - 1 : cx);
    int cy = (int)(y * INV_CS); cy = cy < 0 ? 0 : (cy > NC1 - 1 ? NC1 - 1 : cy);
    int cz = (int)(z * INV_CS); cz = cz < 0 ? 0 : (cz > NC1 - 1 ? NC1 - 1 : cz);
    int cell = (((b * NC1 + cz) * NC1 + cy) * NC1) + cx;
    g_ptcell[i] = cell;
    g_ptslot[i] = atomicAdd(&g_cellcnt[cell], 1);
}

// ---------------- exclusive scan over 2048 cell counts (1 block, shuffle-based) ----
__global__ void k_scan() {
    const unsigned FULL = 0xFFFFFFFFu;
    __shared__ int wsum[32];
    int t = threadIdx.x;           // 0..1023
    int lane = t & 31, w = t >> 5;
    int a = g_cellcnt[2 * t];
    int b = g_cellcnt[2 * t + 1];
    int v = a + b;
    // inclusive warp scan
    int sc = v;
#pragma unroll
    for (int d = 1; d < 32; d <<= 1) {
        int n = __shfl_up_sync(FULL, sc, d);
        if (lane >= d) sc += n;
    }
    if (lane == 31) wsum[w] = sc;
    __syncthreads();
    if (w == 0) {
        int ws = wsum[lane];
#pragma unroll
        for (int d = 1; d < 32; d <<= 1) {
            int n = __shfl_up_sync(FULL, ws, d);
            if (lane >= d) ws += n;
        }
        wsum[lane] = ws;
    }
    __syncthreads();
    int incl = sc + (w > 0 ? wsum[w - 1] : 0);
    int excl = incl - v;
    g_cellstart[2 * t]     = excl;
    g_cellstart[2 * t + 1] = excl + a;
    if (t == 1023) g_cellstart[2048] = incl;
}

// ---------------- scatter: positions into cell order ----------------
__global__ void k_scatter() {
    int i = blockIdx.x * blockDim.x + threadIdx.x;
    if (i >= NPTS) return;
    int t = g_cellstart[g_ptcell[i]] + g_ptslot[i];
    g_ps_sorted[t] = g_p4s[i];
    g_sortidx[t]   = i;
}

// ---------------- neighbor search: one WARP per point ----------------
__global__ void __launch_bounds__(256) k_nbr() {
    const unsigned FULL = 0xFFFFFFFFu;
    int lane = threadIdx.x & 31;
    int i = blockIdx.x * 8 + (threadIdx.x >> 5);
    const float RR = (float)((0.02 * 2.1) * (0.02 * 2.1));
    float4 me = g_p4s[i];
    int b = g_batch[i];
    int cx = (int)(me.x * INV_CS); cx = cx < 0 ? 0 : (cx > NC1 - 1 ? NC1 - 1 : cx);
    int cy = (int)(me.y * INV_CS); cy = cy < 0 ? 0 : (cy > NC1 - 1 ? NC1 - 1 : cy);
    int cz = (int)(me.z * INV_CS); cz = cz < 0 ? 0 : (cz > NC1 - 1 ? NC1 - 1 : cz);
    int x0 = cx > 0 ? cx - 1 : 0;
    int x1 = cx < NC1 - 1 ? cx + 1 : NC1 - 1;
    int z0 = cz > 0 ? cz - 1 : 0, z1 = cz < NC1 - 1 ? cz + 1 : NC1 - 1;
    int y0 = cy > 0 ? cy - 1 : 0, y1 = cy < NC1 - 1 ? cy + 1 : NC1 - 1;
    int cnt = 0;
    int base = i * KNB;
    for (int z = z0; z <= z1; z++) {
        for (int y = y0; y <= y1; y++) {
            int crow = ((b * NC1 + z) * NC1 + y) * NC1;
            int t0 = g_cellstart[crow + x0];
            int t1 = g_cellstart[crow + x1 + 1];
            for (int tb = t0; tb < t1; tb += 32) {
                int t = tb + lane;
                bool hit = false; float d2 = 0.0f; int j = -1;
                if (t < t1) {
                    float4 c = g_ps_sorted[t];
                    float dot = fmaf(me.x, c.x, fmaf(me.y, c.y, me.z * c.z));
                    d2 = (me.w + c.w) - 2.0f * dot;
                    if (d2 < RR) { hit = true; j = g_sortidx[t]; }
                }
                unsigned mask = __ballot_sync(FULL, hit);
                int pos = cnt + __popc(mask & ((1u << lane) - 1u));
                if (hit && pos < KNB) {
                    g_nbr[base + pos]   = j;
                    g_nbrd2[base + pos] = d2;
                }
                int newcnt = cnt + __popc(mask);
                if (newcnt > KNB) {
                    // rare overflow: serial lex-(d2,idx) replacement, t-ascending
                    __syncwarp(FULL);
                    unsigned of = __ballot_sync(FULL, hit && pos >= KNB);
                    while (of) {
                        int src = __ffs(of) - 1;
                        float dd = __shfl_sync(FULL, d2, src);
                        int   jj = __shfl_sync(FULL, j, src);
                        if (lane == 0) {
                            int mxs = 0; float mxd = g_nbrd2[base]; int mxi = g_nbr[base];
                            for (int s = 1; s < KNB; s++) {
                                float d = g_nbrd2[base + s]; int id = g_nbr[base + s];
                                if (d > mxd || (d == mxd && id > mxi)) { mxd = d; mxi = id; mxs = s; }
                            }
                            if (dd < mxd || (dd == mxd && jj < mxi)) {
                                g_nbr[base + mxs] = jj; g_nbrd2[base + mxs] = dd;
                            }
                        }
                        __syncwarp(FULL);
                        of &= of - 1;
                    }
                    cnt = KNB;
                } else {
                    cnt = newcnt;
                }
            }
        }
    }
    int off = 0;
    if (lane == 0) {
        g_cnt[i] = cnt;
        off = atomicAdd(&g_ealloc, cnt);
    }
    off = __shfl_sync(FULL, off, 0);
    if (lane < cnt) g_epack[off + lane] = base + lane;
}

// ---------------- edge-parallel MLP: sums + sumsq + per-point max, no h store ----
// 64 edges per 256-thread block; each thread handles 16 CONSECUTIVE edges
// (amortizes the 72-float weight fill and maximizes per-point max dedup).
#define EDGES_PER_BLK 64
__global__ void __launch_bounds__(256) k_mlp(const float* __restrict__ x,
                                             const float* __restrict__ w1,
                                             const float* __restrict__ b1,
                                             const float* __restrict__ w2,
                                             const float* __restrict__ b2) {
    int E  = g_ealloc;
    int e0 = blockIdx.x * EDGES_PER_BLK;
    if (e0 >= E) return;
    int slot = threadIdx.x >> 6;       // 0..3
    int c    = threadIdx.x & 63;       // channel
    __shared__ float featsm[4][8];
    __shared__ float h1sm[4][CH];
    __shared__ float redsm[4][CH];
    __shared__ float redsm2[4][CH];

    float w1c[8];
#pragma unroll
    for (int f = 0; f < 8; f++) w1c[f] = w1[f * CH + c];
    float w2c[CH];
#pragma unroll
    for (int f = 0; f < CH; f++) w2c[f] = w2[f * CH + c];
    float b1c = b1[c];
    float b2c = b2[c];

    float acc = 0.0f, acc2 = 0.0f;
    int cur_i = -1; unsigned cur_mx = 0u;
#pragma unroll
    for (int it = 0; it < EDGES_PER_BLK / 4; it++) {
        int e = e0 + slot * (EDGES_PER_BLK / 4) + it;  // this thread's edges consecutive
        bool act = (e < E);
        int pk = 0, i = 0, j = 0;
        if (act) {
            pk = g_epack[e];
            i  = pk >> 5;              // KNB = 32
            j  = g_nbr[pk];
        }
        if (act && c < 8) {
            if (c < 4) {
                featsm[slot][c] = x[j * 4 + c];
            } else {
                int f = c - 4;
                featsm[slot][c] = g_pos4[j * 4 + f] - g_pos4[i * 4 + f];
            }
        }
        __syncthreads();
        float h = b1c;
#pragma unroll
        for (int f = 0; f < 8; f++) h = fmaf(featsm[slot][f], w1c[f], h);
        h = (h >= 0.0f) ? h : 0.01f * h;
        h1sm[slot][c] = h;
        __syncthreads();
        float h2 = b2c;
#pragma unroll
        for (int f = 0; f < CH; f++) h2 = fmaf(h1sm[slot][f], w2c[f], h2);
        h2 = (h2 >= 0.0f) ? h2 : 0.01f * h2;
        if (act) {
            acc  += h2;
            acc2  = fmaf(h2, h2, acc2);
            unsigned ord = ford(h2);
            if (i != cur_i) {
                if (cur_i >= 0) atomicMax(&g_maxord[cur_i * CH + c], cur_mx);
                cur_i = i; cur_mx = ord;
            } else if (ord > cur_mx) {
                cur_mx = ord;
            }
        }
        __syncthreads();
    }
    if (cur_i >= 0) atomicMax(&g_maxord[cur_i * CH + c], cur_mx);
    redsm[slot][c]  = acc;
    redsm2[slot][c] = acc2;
    __syncthreads();
    if (slot == 0) {
        float s  = redsm[0][c]  + redsm[1][c]  + redsm[2][c]  + redsm[3][c];
        float s2 = redsm2[0][c] + redsm2[1][c] + redsm2[2][c] + redsm2[3][c];
        atomicAdd(&g_sum[c], s);
        atomicAdd(&g_sumsq[c], s2);
    }
}

// ---------------- BN affine on max + tuple passthrough + cellcnt cleanup -------
// (cellcnt is not read by this kernel, so zeroing it here is race-free;
//  g_maxord is read-then-zeroed by the same thread.)
__global__ void __launch_bounds__(256) k_out(float* __restrict__ out,
                                             const float* __restrict__ gamma,
                                             const float* __restrict__ beta,
                                             const float* __restrict__ pos,
                                             const float* __restrict__ refl,
                                             const float* __restrict__ sf,
                                             int do_pass) {
    int g = threadIdx.x >> 6;
    int c = threadIdx.x & 63;
    int i = blockIdx.x * 4 + g;
    int cnt = g_cnt[i];
    float invE = 1.0f / (float)g_ealloc;
    float mean = g_sum[c] * invE;
    float var  = g_sumsq[c] * invE - mean * mean;
    if (var < 0.0f) var = 0.0f;
    float A = gamma[c] * rsqrtf(var + 1e-5f);
    float B = beta[c] - mean * A;
    unsigned mo = g_maxord[i * CH + c];
    g_maxord[i * CH + c] = 0u;                 // self-clean for next call
    out[i * CH + c] = (cnt > 0) ? fmaf(dord(mo), A, B) : NEGV;

    int idx = blockIdx.x * 256 + threadIdx.x;  // 0 .. 2M (plenty)
    if (idx < NCELLS) g_cellcnt[idx] = 0;      // restore zero-state invariant
    if (!do_pass) return;
    if (idx < 3 * NPTS) {
        out[POS_OFF + idx] = pos[idx];
    } else if (idx < 4 * NPTS) {
        int j = idx - 3 * NPTS;
        out[BATCH_OFF + j] = (float)g_batch[j];
    } else if (idx < 5 * NPTS) {
        int j = idx - 4 * NPTS;
        out[REF_OFF + j] = refl[j];
    } else if (idx < 5 * NPTS + 4) {
        int j = idx - 5 * NPTS;
        out[SF_OFF + j] = sf[j];
    }
}

extern "C" void kernel_launch(void* const* d_in, const int* in_sizes, int n_in,
                              void* d_out, int out_size) {
    const float* x     = (const float*)d_in[0];
    const float* pos   = (const float*)d_in[1];
    const float* refl  = (const float*)d_in[2];
    const float* sf    = (const float*)d_in[3];
    const float* w1    = (const float*)d_in[4];
    const float* b1    = (const float*)d_in[5];
    const float* w2    = (const float*)d_in[6];
    const float* b2    = (const float*)d_in[7];
    const float* gamma = (const float*)d_in[8];
    const float* beta  = (const float*)d_in[9];
    const int*   braw  = (const int*)d_in[10];
    float* out = (float*)d_out;

    k_prep<<<NPTS / 256, 256>>>(pos, refl, sf, braw);
    k_scan<<<1, 1024>>>();
    k_scatter<<<NPTS / 256, 256>>>();
    k_nbr<<<NPTS / 8, 256>>>();
    k_mlp<<<NPTS * KNB / EDGES_PER_BLK, 256>>>(x, w1, b1, w2, b2);
    int do_pass = (out_size >= TOTAL_OUT) ? 1 : 0;
    k_out<<<NPTS / 4, 256>>>(out, gamma, beta, pos, refl, sf, do_pass);
}

// round 13
// speedup vs baseline: 4.0108x; 1.0286x over previous
#include <cuda_runtime.h>
#include <math.h>

#define NPTS 8192
#define KNB  32
#define CH   64
#define NEGV (-1e30f)

#define NC1     8                       // cells per dim
#define NCELLS  (4 * NC1 * NC1 * NC1)   // 2048 (4 batches)
#define INV_CS  20.0f                   // 1 / 0.05 ; 0.05 > R = 0.042

// ---------------- scratch (device globals; no allocation) ----------------
static __device__ float4 g_p4s[NPTS];          // (x, y, z, |p|^2) unscaled
static __device__ float  g_pos4[NPTS * 4];     // (x/s, y/s, z/s, refl)
static __device__ int    g_batch[NPTS];
static __device__ int    g_nbr[NPTS * KNB];
static __device__ float  g_nbrd2[NPTS * KNB];
static __device__ int    g_cnt[NPTS];
static __device__ float  g_Aj[NPTS * CH];      // x_j*W1a + pos4_j*W1b + b1
static __device__ float  g_Bi[NPTS * CH];      // pos4_i*W1b
static __device__ float  g_sum[CH];            // zeroed at start of call (k_prep)
static __device__ float  g_sumsq[CH];
static __device__ unsigned g_maxord[NPTS * CH];// ordered-uint max(h); self-cleaned in k_out
static __device__ int    g_ealloc;             // edge counter (zeroed in k_prep)
static __device__ int    g_epack[NPTS * KNB];  // flattened edges: (i<<13)|j
// cell-list structures
static __device__ int    g_cellcnt[NCELLS];    // zeroed at END of call (k_out merge)
static __device__ int    g_cellstart[NCELLS + 1];
static __device__ int    g_ptcell[NPTS];
static __device__ int    g_ptslot[NPTS];
static __device__ float4 g_ps_sorted[NPTS];    // positions in cell order
static __device__ int    g_sortidx[NPTS];      // sorted slot -> original index

// output layout: out[N,64] | pos[N,3] | batch[N] | reflectance[N] | sf[4]
#define POS_OFF   (NPTS * CH)
#define BATCH_OFF (POS_OFF + NPTS * 3)
#define REF_OFF   (BATCH_OFF + NPTS)
#define SF_OFF    (REF_OFF + NPTS)
#define TOTAL_OUT (SF_OFF + 4)

// monotone float <-> ordered-uint (0 == "below -inf" sentinel)
__device__ __forceinline__ unsigned ford(float f) {
    unsigned u = __float_as_uint(f);
    return (u & 0x80000000u) ? ~u : (u | 0x80000000u);
}
__device__ __forceinline__ float dord(unsigned u) {
    return __uint_as_float((u & 0x80000000u) ? (u & 0x7FFFFFFFu) : ~u);
}

// decode batch element robustly (int32 / int64 / float32-converted)
__device__ __forceinline__ int decode_batch(const int* braw, int i) {
    int last = braw[NPTS - 1];
    int b;
    if (last == 0) {
        b = braw[2 * i];                   // int64 little-endian, low words
    } else if (last >= 1 && last <= 8) {
        b = braw[i];                       // int32
    } else {
        b = (int)__int_as_float(braw[i]);  // stored as float
    }
    if (b < 0) b = 0;
    if (b > 3) b = 3;
    return b;
}

// ---------------- prep: point prep (blocks 0..31) + per-point A/B (all blocks) ----
// grid = NPTS/4 blocks x 256 threads.
// g_cellcnt == 0 on entry (.bss on call 1; re-zeroed by k_out at end of prior call).
__global__ void __launch_bounds__(256) k_prep(const float* __restrict__ pos,
                                              const float* __restrict__ refl,
                                              const float* __restrict__ sf,
                                              const int*   __restrict__ braw,
                                              const float* __restrict__ x,
                                              const float* __restrict__ w1,
                                              const float* __restrict__ b1) {
    int tid = threadIdx.x;
    int idx = blockIdx.x * 256 + tid;

    // ---- part 1: per-point prep (first 8192 global threads) ----
    if (idx < CH) { g_sum[idx] = 0.0f; g_sumsq[idx] = 0.0f; }
    if (idx == 0) g_ealloc = 0;
    if (idx < NPTS) {
        int i = idx;
        int b = decode_batch(braw, i);
        g_batch[i] = b;
        float px = pos[3 * i + 0];
        float py = pos[3 * i + 1];
        float pz = pos[3 * i + 2];
        float sq = fmaf(px, px, fmaf(py, py, pz * pz));
        g_p4s[i] = make_float4(px, py, pz, sq);
        float sc = sf[b];
        g_pos4[4 * i + 0] = px / sc;
        g_pos4[4 * i + 1] = py / sc;
        g_pos4[4 * i + 2] = pz / sc;
        g_pos4[4 * i + 3] = refl[i];
        int cx = (int)(px * INV_CS); cx = cx < 0 ? 0 : (cx > NC1 - 1 ? NC1 - 1 : cx);
        int cy = (int)(py * INV_CS); cy = cy < 0 ? 0 : (cy > NC1 - 1 ? NC1 - 1 : cy);
        int cz = (int)(pz * INV_CS); cz = cz < 0 ? 0 : (cz > NC1 - 1 ? NC1 - 1 : cz);
        int cell = (((b * NC1 + cz) * NC1 + cy) * NC1) + cx;
        g_ptcell[i] = cell;
        g_ptslot[i] = atomicAdd(&g_cellcnt[cell], 1);
    }

    // ---- part 2: A/B precompute, 4 points per block, channel-parallel ----
    int g = tid >> 6;
    int c = tid & 63;
    int i = blockIdx.x * 4 + g;
    __shared__ float p4s[4][4];
    __shared__ float xs[4][4];
    if (c < 4) {
        int b = decode_batch(braw, i);
        float sc = sf[b];
        float v = (c < 3) ? pos[3 * i + c] / sc : refl[i];
        p4s[g][c] = v;
        xs[g][c]  = x[i * 4 + c];
    }
    __syncthreads();
    float w1c[8];
#pragma unroll
    for (int f = 0; f < 8; f++) w1c[f] = w1[f * CH + c];
    float A = b1[c];
#pragma unroll
    for (int f = 0; f < 4; f++) A = fmaf(xs[g][f], w1c[f], A);
#pragma unroll
    for (int f = 0; f < 4; f++) A = fmaf(p4s[g][f], w1c[4 + f], A);
    float B = 0.0f;
#pragma unroll
    for (int f = 0; f < 4; f++) B = fmaf(p4s[g][f], w1c[4 + f], B);
    g_Aj[i * CH + c] = A;
    g_Bi[i * CH + c] = B;
}

// ---------------- exclusive scan over 2048 cell counts (1 block, shuffle-based) ----
__global__ void k_scan() {
    const unsigned FULL = 0xFFFFFFFFu;
    __shared__ int wsum[32];
    int t = threadIdx.x;           // 0..1023
    int lane = t & 31, w = t >> 5;
    int a = g_cellcnt[2 * t];
    int b = g_cellcnt[2 * t + 1];
    int v = a + b;
    int sc = v;
#pragma unroll
    for (int d = 1; d < 32; d <<= 1) {
        int n = __shfl_up_sync(FULL, sc, d);
        if (lane >= d) sc += n;
    }
    if (lane == 31) wsum[w] = sc;
    __syncthreads();
    if (w == 0) {
        int ws = wsum[lane];
#pragma unroll
        for (int d = 1; d < 32; d <<= 1) {
            int n = __shfl_up_sync(FULL, ws, d);
            if (lane >= d) ws += n;
        }
        wsum[lane] = ws;
    }
    __syncthreads();
    int incl = sc + (w > 0 ? wsum[w - 1] : 0);
    int excl = incl - v;
    g_cellstart[2 * t]     = excl;
    g_cellstart[2 * t + 1] = excl + a;
    if (t == 1023) g_cellstart[2048] = incl;
}

// ---------------- scatter: positions into cell order ----------------
__global__ void k_scatter() {
    int i = blockIdx.x * blockDim.x + threadIdx.x;
    if (i >= NPTS) return;
    int t = g_cellstart[g_ptcell[i]] + g_ptslot[i];
    g_ps_sorted[t] = g_p4s[i];
    g_sortidx[t]   = i;
}

// ---------------- neighbor search: one WARP per point ----------------
__global__ void __launch_bounds__(256) k_nbr() {
    const unsigned FULL = 0xFFFFFFFFu;
    int lane = threadIdx.x & 31;
    int i = blockIdx.x * 8 + (threadIdx.x >> 5);
    const float RR = (float)((0.02 * 2.1) * (0.02 * 2.1));
    float4 me = g_p4s[i];
    int b = g_batch[i];
    int cx = (int)(me.x * INV_CS); cx = cx < 0 ? 0 : (cx > NC1 - 1 ? NC1 - 1 : cx);
    int cy = (int)(me.y * INV_CS); cy = cy < 0 ? 0 : (cy > NC1 - 1 ? NC1 - 1 : cy);
    int cz = (int)(me.z * INV_CS); cz = cz < 0 ? 0 : (cz > NC1 - 1 ? NC1 - 1 : cz);
    int x0 = cx > 0 ? cx - 1 : 0;
    int x1 = cx < NC1 - 1 ? cx + 1 : NC1 - 1;
    int z0 = cz > 0 ? cz - 1 : 0, z1 = cz < NC1 - 1 ? cz + 1 : NC1 - 1;
    int y0 = cy > 0 ? cy - 1 : 0, y1 = cy < NC1 - 1 ? cy + 1 : NC1 - 1;
    int cnt = 0;
    int base = i * KNB;
    for (int z = z0; z <= z1; z++) {
        for (int y = y0; y <= y1; y++) {
            int crow = ((b * NC1 + z) * NC1 + y) * NC1;
            int t0 = g_cellstart[crow + x0];
            int t1 = g_cellstart[crow + x1 + 1];
            for (int tb = t0; tb < t1; tb += 32) {
                int t = tb + lane;
                bool hit = false; float d2 = 0.0f; int j = -1;
                if (t < t1) {
                    float4 c = g_ps_sorted[t];
                    float dot = fmaf(me.x, c.x, fmaf(me.y, c.y, me.z * c.z));
                    d2 = (me.w + c.w) - 2.0f * dot;
                    if (d2 < RR) { hit = true; j = g_sortidx[t]; }
                }
                unsigned mask = __ballot_sync(FULL, hit);
                int pos = cnt + __popc(mask & ((1u << lane) - 1u));
                if (hit && pos < KNB) {
                    g_nbr[base + pos]   = j;
                    g_nbrd2[base + pos] = d2;
                }
                int newcnt = cnt + __popc(mask);
                if (newcnt > KNB) {
                    // rare overflow: serial lex-(d2,idx) replacement, t-ascending
                    __syncwarp(FULL);
                    unsigned of = __ballot_sync(FULL, hit && pos >= KNB);
                    while (of) {
                        int src = __ffs(of) - 1;
                        float dd = __shfl_sync(FULL, d2, src);
                        int   jj = __shfl_sync(FULL, j, src);
                        if (lane == 0) {
                            int mxs = 0; float mxd = g_nbrd2[base]; int mxi = g_nbr[base];
                            for (int s = 1; s < KNB; s++) {
                                float d = g_nbrd2[base + s]; int id = g_nbr[base + s];
                                if (d > mxd || (d == mxd && id > mxi)) { mxd = d; mxi = id; mxs = s; }
                            }
                            if (dd < mxd || (dd == mxd && jj < mxi)) {
                                g_nbr[base + mxs] = jj; g_nbrd2[base + mxs] = dd;
                            }
                        }
                        __syncwarp(FULL);
                        of &= of - 1;
                    }
                    cnt = KNB;
                } else {
                    cnt = newcnt;
                }
            }
        }
    }
    int off = 0;
    if (lane == 0) {
        g_cnt[i] = cnt;
        off = atomicAdd(&g_ealloc, cnt);
    }
    off = __shfl_sync(FULL, off, 0);
    if (lane < cnt) g_epack[off + lane] = (i << 13) | g_nbr[base + lane];
}

// ---------------- edge-parallel MLP: layer1 = lrelu(A[j]-B[i]), layer2 dense ----
// 128 edges per 256-thread block; each thread: 32 CONSECUTIVE edges.
#define EDGES_PER_BLK 128
__global__ void __launch_bounds__(256) k_mlp(const float* __restrict__ w2,
                                             const float* __restrict__ b2) {
    int E  = g_ealloc;
    int e0 = blockIdx.x * EDGES_PER_BLK;
    if (e0 >= E) return;
    int slot = threadIdx.x >> 6;       // 0..3
    int c    = threadIdx.x & 63;       // channel
    __shared__ float h1sm[4][CH];
    __shared__ float redsm[4][CH];
    __shared__ float redsm2[4][CH];

    float w2c[CH];
#pragma unroll
    for (int f = 0; f < CH; f++) w2c[f] = w2[f * CH + c];
    float b2c = b2[c];

    float acc = 0.0f, acc2 = 0.0f;
    int cur_i = -1; unsigned cur_mx = 0u;
#pragma unroll 1
    for (int it = 0; it < EDGES_PER_BLK / 4; it++) {
        int e = e0 + slot * (EDGES_PER_BLK / 4) + it;  // this thread's edges consecutive
        bool act = (e < E);
        int i = 0;
        float h = 0.0f;
        if (act) {
            int p = g_epack[e];
            i     = p >> 13;
            int j = p & 8191;
            h = g_Aj[j * CH + c] - g_Bi[i * CH + c];   // layer1 pre-activation
        }
        h = (h >= 0.0f) ? h : 0.01f * h;
        h1sm[slot][c] = h;
        __syncthreads();
        float h2 = b2c;
#pragma unroll
        for (int f = 0; f < CH; f++) h2 = fmaf(h1sm[slot][f], w2c[f], h2);
        h2 = (h2 >= 0.0f) ? h2 : 0.01f * h2;
        if (act) {
            acc  += h2;
            acc2  = fmaf(h2, h2, acc2);
            unsigned ord = ford(h2);
            if (i != cur_i) {
                if (cur_i >= 0) atomicMax(&g_maxord[cur_i * CH + c], cur_mx);
                cur_i = i; cur_mx = ord;
            } else if (ord > cur_mx) {
                cur_mx = ord;
            }
        }
        __syncthreads();
    }
    if (cur_i >= 0) atomicMax(&g_maxord[cur_i * CH + c], cur_mx);
    redsm[slot][c]  = acc;
    redsm2[slot][c] = acc2;
    __syncthreads();
    if (slot == 0) {
        float s  = redsm[0][c]  + redsm[1][c]  + redsm[2][c]  + redsm[3][c];
        float s2 = redsm2[0][c] + redsm2[1][c] + redsm2[2][c] + redsm2[3][c];
        atomicAdd(&g_sum[c], s);
        atomicAdd(&g_sumsq[c], s2);
    }
}

// ---------------- BN affine on max + tuple passthrough + cellcnt cleanup -------
__global__ void __launch_bounds__(256) k_out(float* __restrict__ out,
                                             const float* __restrict__ gamma,
                                             const float* __restrict__ beta,
                                             const float* __restrict__ pos,
                                             const float* __restrict__ refl,
                                             const float* __restrict__ sf,
                                             int do_pass) {
    int g = threadIdx.x >> 6;
    int c = threadIdx.x & 63;
    int i = blockIdx.x * 4 + g;
    int cnt = g_cnt[i];
    float invE = 1.0f / (float)g_ealloc;
    float mean = g_sum[c] * invE;
    float var  = g_sumsq[c] * invE - mean * mean;
    if (var < 0.0f) var = 0.0f;
    float A = gamma[c] * rsqrtf(var + 1e-5f);
    float B = beta[c] - mean * A;
    unsigned mo = g_maxord[i * CH + c];
    g_maxord[i * CH + c] = 0u;                 // self-clean for next call
    out[i * CH + c] = (cnt > 0) ? fmaf(dord(mo), A, B) : NEGV;

    int idx = blockIdx.x * 256 + threadIdx.x;
    if (idx < NCELLS) g_cellcnt[idx] = 0;      // restore zero-state invariant
    if (!do_pass) return;
    if (idx < 3 * NPTS) {
        out[POS_OFF + idx] = pos[idx];
    } else if (idx < 4 * NPTS) {
        int j = idx - 3 * NPTS;
        out[BATCH_OFF + j] = (float)g_batch[j];
    } else if (idx < 5 * NPTS) {
        int j = idx - 4 * NPTS;
        out[REF_OFF + j] = refl[j];
    } else if (idx < 5 * NPTS + 4) {
        int j = idx - 5 * NPTS;
        out[SF_OFF + j] = sf[j];
    }
}

extern "C" void kernel_launch(void* const* d_in, const int* in_sizes, int n_in,
                              void* d_out, int out_size) {
    const float* x     = (const float*)d_in[0];
    const float* pos   = (const float*)d_in[1];
    const float* refl  = (const float*)d_in[2];
    const float* sf    = (const float*)d_in[3];
    const float* w1    = (const float*)d_in[4];
    const float* b1    = (const float*)d_in[5];
    const float* w2    = (const float*)d_in[6];
    const float* b2    = (const float*)d_in[7];
    const float* gamma = (const float*)d_in[8];
    const float* beta  = (const float*)d_in[9];
    const int*   braw  = (const int*)d_in[10];
    float* out = (float*)d_out;

    k_prep<<<NPTS / 4, 256>>>(pos, refl, sf, braw, x, w1, b1);
    k_scan<<<1, 1024>>>();
    k_scatter<<<NPTS / 256, 256>>>();
    k_nbr<<<NPTS / 8, 256>>>();
    k_mlp<<<NPTS * KNB / EDGES_PER_BLK, 256>>>(w2, b2);
    int do_pass = (out_size >= TOTAL_OUT) ? 1 : 0;
    k_out<<<NPTS / 4, 256>>>(out, gamma, beta, pos, refl, sf, do_pass);
}

// round 15
// speedup vs baseline: 4.1738x; 1.0406x over previous
#include <cuda_runtime.h>
#include <math.h>

#define NPTS 8192
#define KNB  32
#define CH   64
#define NEGV (-1e30f)

#define NC1     8                       // cells per dim
#define NCELLS  (4 * NC1 * NC1 * NC1)   // 2048 (4 batches)
#define INV_CS  20.0f                   // 1 / 0.05 ; 0.05 > R = 0.042

typedef unsigned long long u64;

// ---------------- scratch (device globals; no allocation) ----------------
static __device__ float4 g_p4s[NPTS];          // (x, y, z, |p|^2) unscaled
static __device__ float  g_pos4[NPTS * 4];     // (x/s, y/s, z/s, refl)
static __device__ int    g_batch[NPTS];
static __device__ int    g_nbr[NPTS * KNB];
static __device__ float  g_nbrd2[NPTS * KNB];
static __device__ int    g_cnt[NPTS];
static __device__ float  g_Aj[NPTS * CH];      // x_j*W1a + pos4_j*W1b + b1
static __device__ float  g_Bi[NPTS * CH];      // pos4_i*W1b
static __device__ float  g_sum[CH];            // zeroed at start of call (k_prep)
static __device__ float  g_sumsq[CH];
static __device__ unsigned g_maxord[NPTS * CH];// ordered-uint max(h); self-cleaned in k_out
static __device__ int    g_ealloc;             // edge counter (zeroed in k_prep)
static __device__ int    g_epack[NPTS * KNB];  // flattened edges: (i<<13)|j
// cell-list structures
static __device__ int    g_cellcnt[NCELLS];    // zeroed at END of call (k_out merge)
static __device__ int    g_cellstart[NCELLS + 1];
static __device__ int    g_ptcell[NPTS];
static __device__ int    g_ptslot[NPTS];
static __device__ float4 g_ps_sorted[NPTS];    // positions in cell order
static __device__ int    g_sortidx[NPTS];      // sorted slot -> original index

// output layout: out[N,64] | pos[N,3] | batch[N] | reflectance[N] | sf[4]
#define POS_OFF   (NPTS * CH)
#define BATCH_OFF (POS_OFF + NPTS * 3)
#define REF_OFF   (BATCH_OFF + NPTS)
#define SF_OFF    (REF_OFF + NPTS)
#define TOTAL_OUT (SF_OFF + 4)

// ---------------- packed f32x2 helpers (FFMA2 path, PTX-only) ----------------
__device__ __forceinline__ u64 pack2(float lo, float hi) {
    u64 r; asm("mov.b64 %0, {%1, %2};" : "=l"(r) : "f"(lo), "f"(hi)); return r;
}
__device__ __forceinline__ void unpack2(u64 v, float& lo, float& hi) {
    asm("mov.b64 {%0, %1}, %2;" : "=f"(lo), "=f"(hi) : "l"(v));
}
__device__ __forceinline__ u64 ffma2(u64 a, u64 b, u64 c) {
    u64 d; asm("fma.rn.f32x2 %0, %1, %2, %3;" : "=l"(d) : "l"(a), "l"(b), "l"(c)); return d;
}

// monotone float <-> ordered-uint (0 == "below -inf" sentinel)
__device__ __forceinline__ unsigned ford(float f) {
    unsigned u = __float_as_uint(f);
    return (u & 0x80000000u) ? ~u : (u | 0x80000000u);
}
__device__ __forceinline__ float dord(unsigned u) {
    return __uint_as_float((u & 0x80000000u) ? (u & 0x7FFFFFFFu) : ~u);
}

// decode batch element robustly (int32 / int64 / float32-converted)
__device__ __forceinline__ int decode_batch(const int* braw, int i) {
    int last = braw[NPTS - 1];
    int b;
    if (last == 0) {
        b = braw[2 * i];                   // int64 little-endian, low words
    } else if (last >= 1 && last <= 8) {
        b = braw[i];                       // int32
    } else {
        b = (int)__int_as_float(braw[i]);  // stored as float
    }
    if (b < 0) b = 0;
    if (b > 3) b = 3;
    return b;
}

// ---------------- prep: point prep + per-point A/B precompute ----------------
// grid = NPTS/4 blocks x 256 threads.
// g_cellcnt == 0 on entry (.bss on call 1; re-zeroed by k_out at end of prior call).
__global__ void __launch_bounds__(256) k_prep(const float* __restrict__ pos,
                                              const float* __restrict__ refl,
                                              const float* __restrict__ sf,
                                              const int*   __restrict__ braw,
                                              const float* __restrict__ x,
                                              const float* __restrict__ w1,
                                              const float* __restrict__ b1) {
    int tid = threadIdx.x;
    int idx = blockIdx.x * 256 + tid;

    // ---- part 1: per-point prep (first 8192 global threads) ----
    if (idx < CH) { g_sum[idx] = 0.0f; g_sumsq[idx] = 0.0f; }
    if (idx == 0) g_ealloc = 0;
    if (idx < NPTS) {
        int i = idx;
        int b = decode_batch(braw, i);
        g_batch[i] = b;
        float px = pos[3 * i + 0];
        float py = pos[3 * i + 1];
        float pz = pos[3 * i + 2];
        float sq = fmaf(px, px, fmaf(py, py, pz * pz));
        g_p4s[i] = make_float4(px, py, pz, sq);
        float sc = sf[b];
        g_pos4[4 * i + 0] = px / sc;
        g_pos4[4 * i + 1] = py / sc;
        g_pos4[4 * i + 2] = pz / sc;
        g_pos4[4 * i + 3] = refl[i];
        int cx = (int)(px * INV_CS); cx = cx < 0 ? 0 : (cx > NC1 - 1 ? NC1 - 1 : cx);
        int cy = (int)(py * INV_CS); cy = cy < 0 ? 0 : (cy > NC1 - 1 ? NC1 - 1 : cy);
        int cz = (int)(pz * INV_CS); cz = cz < 0 ? 0 : (cz > NC1 - 1 ? NC1 - 1 : cz);
        int cell = (((b * NC1 + cz) * NC1 + cy) * NC1) + cx;
        g_ptcell[i] = cell;
        g_ptslot[i] = atomicAdd(&g_cellcnt[cell], 1);
    }

    // ---- part 2: A/B precompute, 4 points per block, channel-parallel ----
    int g = tid >> 6;
    int c = tid & 63;
    int i = blockIdx.x * 4 + g;
    __shared__ float p4s[4][4];
    __shared__ float xs[4][4];
    if (c < 4) {
        int b = decode_batch(braw, i);
        float sc = sf[b];
        float v = (c < 3) ? pos[3 * i + c] / sc : refl[i];
        p4s[g][c] = v;
        xs[g][c]  = x[i * 4 + c];
    }
    __syncthreads();
    float w1c[8];
#pragma unroll
    for (int f = 0; f < 8; f++) w1c[f] = w1[f * CH + c];
    float A = b1[c];
#pragma unroll
    for (int f = 0; f < 4; f++) A = fmaf(xs[g][f], w1c[f], A);
#pragma unroll
    for (int f = 0; f < 4; f++) A = fmaf(p4s[g][f], w1c[4 + f], A);
    float B = 0.0f;
#pragma unroll
    for (int f = 0; f < 4; f++) B = fmaf(p4s[g][f], w1c[4 + f], B);
    g_Aj[i * CH + c] = A;
    g_Bi[i * CH + c] = B;
}

// ---------------- scatter (with redundant per-block scan of 2048 cell counts) ----
// grid = 32 x 256. Each block scans all cell counts in smem (cheap, parallel),
// scatters its 256 points, and block 0 publishes g_cellstart for k_nbr.
__global__ void __launch_bounds__(256) k_scatter() {
    const unsigned FULL = 0xFFFFFFFFu;
    __shared__ int s_start[NCELLS];
    __shared__ int wsum[8];
    int t = threadIdx.x;
    int lane = t & 31, w = t >> 5;
    // load 8 consecutive counts per thread
    int v[8]; int tot = 0;
#pragma unroll
    for (int k = 0; k < 8; k++) { v[k] = g_cellcnt[t * 8 + k]; tot += v[k]; }
    // warp inclusive scan of thread totals
    int sc = tot;
#pragma unroll
    for (int d = 1; d < 32; d <<= 1) {
        int n = __shfl_up_sync(FULL, sc, d);
        if (lane >= d) sc += n;
    }
    if (lane == 31) wsum[w] = sc;
    __syncthreads();
    int wbase = 0;
#pragma unroll
    for (int q = 0; q < 8; q++) wbase += (q < w) ? wsum[q] : 0;
    int run = wbase + sc - tot;        // exclusive prefix for this thread's chunk
#pragma unroll
    for (int k = 0; k < 8; k++) { s_start[t * 8 + k] = run; run += v[k]; }
    __syncthreads();
    // block 0 publishes cellstart for k_nbr
    if (blockIdx.x == 0) {
        for (int u = t; u < NCELLS; u += 256) g_cellstart[u] = s_start[u];
        if (t == 0) g_cellstart[NCELLS] = NPTS;
    }
    // scatter this block's 256 points
    int i = blockIdx.x * 256 + t;
    int p = s_start[g_ptcell[i]] + g_ptslot[i];
    g_ps_sorted[p] = g_p4s[i];
    g_sortidx[p]   = i;
}

// ---------------- neighbor search: one WARP per point ----------------
__global__ void __launch_bounds__(256) k_nbr() {
    const unsigned FULL = 0xFFFFFFFFu;
    int lane = threadIdx.x & 31;
    int i = blockIdx.x * 8 + (threadIdx.x >> 5);
    const float RR = (float)((0.02 * 2.1) * (0.02 * 2.1));
    float4 me = g_p4s[i];
    int b = g_batch[i];
    int cx = (int)(me.x * INV_CS); cx = cx < 0 ? 0 : (cx > NC1 - 1 ? NC1 - 1 : cx);
    int cy = (int)(me.y * INV_CS); cy = cy < 0 ? 0 : (cy > NC1 - 1 ? NC1 - 1 : cy);
    int cz = (int)(me.z * INV_CS); cz = cz < 0 ? 0 : (cz > NC1 - 1 ? NC1 - 1 : cz);
    int x0 = cx > 0 ? cx - 1 : 0;
    int x1 = cx < NC1 - 1 ? cx + 1 : NC1 - 1;
    int z0 = cz > 0 ? cz - 1 : 0, z1 = cz < NC1 - 1 ? cz + 1 : NC1 - 1;
    int y0 = cy > 0 ? cy - 1 : 0, y1 = cy < NC1 - 1 ? cy + 1 : NC1 - 1;
    int cnt = 0;
    int base = i * KNB;
    for (int z = z0; z <= z1; z++) {
        for (int y = y0; y <= y1; y++) {
            int crow = ((b * NC1 + z) * NC1 + y) * NC1;
            int t0 = g_cellstart[crow + x0];
            int t1 = g_cellstart[crow + x1 + 1];
            for (int tb = t0; tb < t1; tb += 32) {
                int t = tb + lane;
                bool hit = false; float d2 = 0.0f; int j = -1;
                if (t < t1) {
                    float4 c = g_ps_sorted[t];
                    float dot = fmaf(me.x, c.x, fmaf(me.y, c.y, me.z * c.z));
                    d2 = (me.w + c.w) - 2.0f * dot;
                    if (d2 < RR) { hit = true; j = g_sortidx[t]; }
                }
                unsigned mask = __ballot_sync(FULL, hit);
                int pos = cnt + __popc(mask & ((1u << lane) - 1u));
                if (hit && pos < KNB) {
                    g_nbr[base + pos]   = j;
                    g_nbrd2[base + pos] = d2;
                }
                int newcnt = cnt + __popc(mask);
                if (newcnt > KNB) {
                    // rare overflow: serial lex-(d2,idx) replacement, t-ascending
                    __syncwarp(FULL);
                    unsigned of = __ballot_sync(FULL, hit && pos >= KNB);
                    while (of) {
                        int src = __ffs(of) - 1;
                        float dd = __shfl_sync(FULL, d2, src);
                        int   jj = __shfl_sync(FULL, j, src);
                        if (lane == 0) {
                            int mxs = 0; float mxd = g_nbrd2[base]; int mxi = g_nbr[base];
                            for (int s = 1; s < KNB; s++) {
                                float d = g_nbrd2[base + s]; int id = g_nbr[base + s];
                                if (d > mxd || (d == mxd && id > mxi)) { mxd = d; mxi = id; mxs = s; }
                            }
                            if (dd < mxd || (dd == mxd && jj < mxi)) {
                                g_nbr[base + mxs] = jj; g_nbrd2[base + mxs] = dd;
                            }
                        }
                        __syncwarp(FULL);
                        of &= of - 1;
                    }
                    cnt = KNB;
                } else {
                    cnt = newcnt;
                }
            }
        }
    }
    int off = 0;
    if (lane == 0) {
        g_cnt[i] = cnt;
        off = atomicAdd(&g_ealloc, cnt);
    }
    off = __shfl_sync(FULL, off, 0);
    if (lane < cnt) g_epack[off + lane] = (i << 13) | g_nbr[base + lane];
}

// ---------------- edge-parallel MLP: layer1 = lrelu(A[j]-B[i]), packed layer2 ----
// 128 edges per 256-thread block; each thread: 32 CONSECUTIVE edges.
#define EDGES_PER_BLK 128
__global__ void __launch_bounds__(256) k_mlp(const float* __restrict__ w2,
                                             const float* __restrict__ b2) {
    int E  = g_ealloc;
    int e0 = blockIdx.x * EDGES_PER_BLK;
    if (e0 >= E) return;
    int slot = threadIdx.x >> 6;       // 0..3
    int c    = threadIdx.x & 63;       // channel
    __shared__ float h1sm[4][CH];      // read back as float2 pairs
    __shared__ float redsm[4][CH];
    __shared__ float redsm2[4][CH];

    // packed column of W2: pairs over the f (input) dimension
    u64 w2p[CH / 2];
#pragma unroll
    for (int f2 = 0; f2 < CH / 2; f2++)
        w2p[f2] = pack2(w2[(2 * f2) * CH + c], w2[(2 * f2 + 1) * CH + c]);
    float b2c = b2[c];

    float acc = 0.0f, acc2 = 0.0f;
    int cur_i = -1; unsigned cur_mx = 0u;
#pragma unroll 1
    for (int it = 0; it < EDGES_PER_BLK / 4; it++) {
        int e = e0 + slot * (EDGES_PER_BLK / 4) + it;  // this thread's edges consecutive
        bool act = (e < E);
        int i = 0;
        float h = 0.0f;
        if (act) {
            int p = g_epack[e];
            i     = p >> 13;
            int j = p & 8191;
            h = g_Aj[j * CH + c] - g_Bi[i * CH + c];   // layer1 pre-activation
        }
        h = (h >= 0.0f) ? h : 0.01f * h;
        h1sm[slot][c] = h;
        __syncthreads();
        const float2* h1p = (const float2*)h1sm[slot];
        u64 accp = pack2(0.0f, 0.0f);
#pragma unroll
        for (int f2 = 0; f2 < CH / 2; f2++) {
            float2 hv = h1p[f2];
            accp = ffma2(pack2(hv.x, hv.y), w2p[f2], accp);
        }
        float lo, hi; unpack2(accp, lo, hi);
        float h2 = b2c + lo + hi;
        h2 = (h2 >= 0.0f) ? h2 : 0.01f * h2;
        if (act) {
            acc  += h2;
            acc2  = fmaf(h2, h2, acc2);
            unsigned ord = ford(h2);
            if (i != cur_i) {
                if (cur_i >= 0) atomicMax(&g_maxord[cur_i * CH + c], cur_mx);
                cur_i = i; cur_mx = ord;
            } else if (ord > cur_mx) {
                cur_mx = ord;
            }
        }
        __syncthreads();
    }
    if (cur_i >= 0) atomicMax(&g_maxord[cur_i * CH + c], cur_mx);
    redsm[slot][c]  = acc;
    redsm2[slot][c] = acc2;
    __syncthreads();
    if (slot == 0) {
        float s  = redsm[0][c]  + redsm[1][c]  + redsm[2][c]  + redsm[3][c];
        float s2 = redsm2[0][c] + redsm2[1][c] + redsm2[2][c] + redsm2[3][c];
        atomicAdd(&g_sum[c], s);
        atomicAdd(&g_sumsq[c], s2);
    }
}

// ---------------- BN affine on max + tuple passthrough + cellcnt cleanup -------
__global__ void __launch_bounds__(256) k_out(float* __restrict__ out,
                                             const float* __restrict__ gamma,
                                             const float* __restrict__ beta,
                                             const float* __restrict__ pos,
                                             const float* __restrict__ refl,
                                             const float* __restrict__ sf,
                                             int do_pass) {
    int g = threadIdx.x >> 6;
    int c = threadIdx.x & 63;
    int i = blockIdx.x * 4 + g;
    int cnt = g_cnt[i];
    float invE = 1.0f / (float)g_ealloc;
    float mean = g_sum[c] * invE;
    float var  = g_sumsq[c] * invE - mean * mean;
    if (var < 0.0f) var = 0.0f;
    float A = gamma[c] * rsqrtf(var + 1e-5f);
    float B = beta[c] - mean * A;
    unsigned mo = g_maxord[i * CH + c];
    g_maxord[i * CH + c] = 0u;                 // self-clean for next call
    out[i * CH + c] = (cnt > 0) ? fmaf(dord(mo), A, B) : NEGV;

    int idx = blockIdx.x * 256 + threadIdx.x;
    if (idx < NCELLS) g_cellcnt[idx] = 0;      // restore zero-state invariant
    if (!do_pass) return;
    if (idx < 3 * NPTS) {
        out[POS_OFF + idx] = pos[idx];
    } else if (idx < 4 * NPTS) {
        int j = idx - 3 * NPTS;
        out[BATCH_OFF + j] = (float)g_batch[j];
    } else if (idx < 5 * NPTS) {
        int j = idx - 4 * NPTS;
        out[REF_OFF + j] = refl[j];
    } else if (idx < 5 * NPTS + 4) {
        int j = idx - 5 * NPTS;
        out[SF_OFF + j] = sf[j];
    }
}

extern "C" void kernel_launch(void* const* d_in, const int* in_sizes, int n_in,
                              void* d_out, int out_size) {
    const float* x     = (const float*)d_in[0];
    const float* pos   = (const float*)d_in[1];
    const float* refl  = (const float*)d_in[2];
    const float* sf    = (const float*)d_in[3];
    const float* w1    = (const float*)d_in[4];
    const float* b1    = (const float*)d_in[5];
    const float* w2    = (const float*)d_in[6];
    const float* b2    = (const float*)d_in[7];
    const float* gamma = (const float*)d_in[8];
    const float* beta  = (const float*)d_in[9];
    const int*   braw  = (const int*)d_in[10];
    float* out = (float*)d_out;

    k_prep<<<NPTS / 4, 256>>>(pos, refl, sf, braw, x, w1, b1);
    k_scatter<<<NPTS / 256, 256>>>();
    k_nbr<<<NPTS / 8, 256>>>();
    k_mlp<<<NPTS * KNB / EDGES_PER_BLK, 256>>>(w2, b2);
    int do_pass = (out_size >= TOTAL_OUT) ? 1 : 0;
    k_out<<<NPTS / 4, 256>>>(out, gamma, beta, pos, refl, sf, do_pass);
}

// round 17
// speedup vs baseline: 4.1786x; 1.0012x over previous
#include <cuda_runtime.h>
#include <math.h>

#define NPTS 8192
#define KNB  32
#define CH   64
#define NEGV (-1e30f)

#define NC1     8                       // cells per dim
#define NCELLS  (4 * NC1 * NC1 * NC1)   // 2048 (4 batches)
#define INV_CS  20.0f                   // 1 / 0.05 ; 0.05 > R = 0.042

typedef unsigned long long u64;

// ---------------- scratch (device globals; no allocation) ----------------
static __device__ float4 g_p4s[NPTS];          // (x, y, z, |p|^2) unscaled
static __device__ float  g_pos4[NPTS * 4];     // (x/s, y/s, z/s, refl)
static __device__ int    g_batch[NPTS];
static __device__ int    g_nbr[NPTS * KNB];
static __device__ float  g_nbrd2[NPTS * KNB];
static __device__ int    g_cnt[NPTS];
static __device__ float  g_Aj[NPTS * CH];      // x_j*W1a + pos4_j*W1b + b1
static __device__ float  g_Bi[NPTS * CH];      // pos4_i*W1b
static __device__ float  g_sum[CH];            // zeroed at start of call (k_prep)
static __device__ float  g_sumsq[CH];
static __device__ unsigned g_maxord[NPTS * CH];// ordered-uint max(h); self-cleaned in k_out
static __device__ int    g_ealloc;             // edge counter (zeroed in k_prep)
static __device__ int    g_epack[NPTS * KNB];  // flattened edges: (i<<13)|j
// cell-list structures
static __device__ int    g_cellcnt[NCELLS];    // zeroed at END of call (k_out merge)
static __device__ int    g_cellstart[NCELLS + 1];
static __device__ int    g_ptcell[NPTS];
static __device__ int    g_ptslot[NPTS];
static __device__ float4 g_ps_sorted[NPTS];    // positions in cell order
static __device__ int    g_sortidx[NPTS];      // sorted slot -> original index

// output layout: out[N,64] | pos[N,3] | batch[N] | reflectance[N] | sf[4]
#define POS_OFF   (NPTS * CH)
#define BATCH_OFF (POS_OFF + NPTS * 3)
#define REF_OFF   (BATCH_OFF + NPTS)
#define SF_OFF    (REF_OFF + NPTS)
#define TOTAL_OUT (SF_OFF + 4)

// ---------------- packed f32x2 helpers (FFMA2 path, PTX-only) ----------------
__device__ __forceinline__ u64 pack2(float lo, float hi) {
    u64 r; asm("mov.b64 %0, {%1, %2};" : "=l"(r) : "f"(lo), "f"(hi)); return r;
}
__device__ __forceinline__ void unpack2(u64 v, float& lo, float& hi) {
    asm("mov.b64 {%0, %1}, %2;" : "=f"(lo), "=f"(hi) : "l"(v));
}
__device__ __forceinline__ u64 ffma2(u64 a, u64 b, u64 c) {
    u64 d; asm("fma.rn.f32x2 %0, %1, %2, %3;" : "=l"(d) : "l"(a), "l"(b), "l"(c)); return d;
}
__device__ __forceinline__ u64 fadd2(u64 a, u64 b) {
    u64 d; asm("add.rn.f32x2 %0, %1, %2;" : "=l"(d) : "l"(a), "l"(b)); return d;
}

// monotone float <-> ordered-uint (0 == "below -inf" sentinel)
__device__ __forceinline__ unsigned ford(float f) {
    unsigned u = __float_as_uint(f);
    return (u & 0x80000000u) ? ~u : (u | 0x80000000u);
}
__device__ __forceinline__ float dord(unsigned u) {
    return __uint_as_float((u & 0x80000000u) ? (u & 0x7FFFFFFFu) : ~u);
}

// decode batch element robustly (int32 / int64 / float32-converted)
__device__ __forceinline__ int decode_batch(const int* braw, int i) {
    int last = braw[NPTS - 1];
    int b;
    if (last == 0) {
        b = braw[2 * i];                   // int64 little-endian, low words
    } else if (last >= 1 && last <= 8) {
        b = braw[i];                       // int32
    } else {
        b = (int)__int_as_float(braw[i]);  // stored as float
    }
    if (b < 0) b = 0;
    if (b > 3) b = 3;
    return b;
}

// ---------------- prep: point prep + per-point A/B precompute ----------------
__global__ void __launch_bounds__(256) k_prep(const float* __restrict__ pos,
                                              const float* __restrict__ refl,
                                              const float* __restrict__ sf,
                                              const int*   __restrict__ braw,
                                              const float* __restrict__ x,
                                              const float* __restrict__ w1,
                                              const float* __restrict__ b1) {
    int tid = threadIdx.x;
    int idx = blockIdx.x * 256 + tid;

    if (idx < CH) { g_sum[idx] = 0.0f; g_sumsq[idx] = 0.0f; }
    if (idx == 0) g_ealloc = 0;
    if (idx < NPTS) {
        int i = idx;
        int b = decode_batch(braw, i);
        g_batch[i] = b;
        float px = pos[3 * i + 0];
        float py = pos[3 * i + 1];
        float pz = pos[3 * i + 2];
        float sq = fmaf(px, px, fmaf(py, py, pz * pz));
        g_p4s[i] = make_float4(px, py, pz, sq);
        float sc = sf[b];
        g_pos4[4 * i + 0] = px / sc;
        g_pos4[4 * i + 1] = py / sc;
        g_pos4[4 * i + 2] = pz / sc;
        g_pos4[4 * i + 3] = refl[i];
        int cx = (int)(px * INV_CS); cx = cx < 0 ? 0 : (cx > NC1 - 1 ? NC1 - 1 : cx);
        int cy = (int)(py * INV_CS); cy = cy < 0 ? 0 : (cy > NC1 - 1 ? NC1 - 1 : cy);
        int cz = (int)(pz * INV_CS); cz = cz < 0 ? 0 : (cz > NC1 - 1 ? NC1 - 1 : cz);
        int cell = (((b * NC1 + cz) * NC1 + cy) * NC1) + cx;
        g_ptcell[i] = cell;
        g_ptslot[i] = atomicAdd(&g_cellcnt[cell], 1);
    }

    int g = tid >> 6;
    int c = tid & 63;
    int i = blockIdx.x * 4 + g;
    __shared__ float p4s[4][4];
    __shared__ float xs[4][4];
    if (c < 4) {
        int b = decode_batch(braw, i);
        float sc = sf[b];
        float v = (c < 3) ? pos[3 * i + c] / sc : refl[i];
        p4s[g][c] = v;
        xs[g][c]  = x[i * 4 + c];
    }
    __syncthreads();
    float w1c[8];
#pragma unroll
    for (int f = 0; f < 8; f++) w1c[f] = w1[f * CH + c];
    float A = b1[c];
#pragma unroll
    for (int f = 0; f < 4; f++) A = fmaf(xs[g][f], w1c[f], A);
#pragma unroll
    for (int f = 0; f < 4; f++) A = fmaf(p4s[g][f], w1c[4 + f], A);
    float B = 0.0f;
#pragma unroll
    for (int f = 0; f < 4; f++) B = fmaf(p4s[g][f], w1c[4 + f], B);
    g_Aj[i * CH + c] = A;
    g_Bi[i * CH + c] = B;
}

// ---------------- scatter (with redundant per-block scan of 2048 cell counts) ----
__global__ void __launch_bounds__(256) k_scatter() {
    const unsigned FULL = 0xFFFFFFFFu;
    __shared__ int s_start[NCELLS];
    __shared__ int wsum[8];
    int t = threadIdx.x;
    int lane = t & 31, w = t >> 5;
    int v[8]; int tot = 0;
#pragma unroll
    for (int k = 0; k < 8; k++) { v[k] = g_cellcnt[t * 8 + k]; tot += v[k]; }
    int sc = tot;
#pragma unroll
    for (int d = 1; d < 32; d <<= 1) {
        int n = __shfl_up_sync(FULL, sc, d);
        if (lane >= d) sc += n;
    }
    if (lane == 31) wsum[w] = sc;
    __syncthreads();
    int wbase = 0;
#pragma unroll
    for (int q = 0; q < 8; q++) wbase += (q < w) ? wsum[q] : 0;
    int run = wbase + sc - tot;
#pragma unroll
    for (int k = 0; k < 8; k++) { s_start[t * 8 + k] = run; run += v[k]; }
    __syncthreads();
    if (blockIdx.x == 0) {
        for (int u = t; u < NCELLS; u += 256) g_cellstart[u] = s_start[u];
        if (t == 0) g_cellstart[NCELLS] = NPTS;
    }
    int i = blockIdx.x * 256 + t;
    int p = s_start[g_ptcell[i]] + g_ptslot[i];
    g_ps_sorted[p] = g_p4s[i];
    g_sortidx[p]   = i;
}

// ---------------- neighbor search: one WARP per point ----------------
__global__ void __launch_bounds__(256) k_nbr() {
    const unsigned FULL = 0xFFFFFFFFu;
    int lane = threadIdx.x & 31;
    int i = blockIdx.x * 8 + (threadIdx.x >> 5);
    const float RR = (float)((0.02 * 2.1) * (0.02 * 2.1));
    float4 me = g_p4s[i];
    int b = g_batch[i];
    int cx = (int)(me.x * INV_CS); cx = cx < 0 ? 0 : (cx > NC1 - 1 ? NC1 - 1 : cx);
    int cy = (int)(me.y * INV_CS); cy = cy < 0 ? 0 : (cy > NC1 - 1 ? NC1 - 1 : cy);
    int cz = (int)(me.z * INV_CS); cz = cz < 0 ? 0 : (cz > NC1 - 1 ? NC1 - 1 : cz);
    int x0 = cx > 0 ? cx - 1 : 0;
    int x1 = cx < NC1 - 1 ? cx + 1 : NC1 - 1;
    int z0 = cz > 0 ? cz - 1 : 0, z1 = cz < NC1 - 1 ? cz + 1 : NC1 - 1;
    int y0 = cy > 0 ? cy - 1 : 0, y1 = cy < NC1 - 1 ? cy + 1 : NC1 - 1;
    int cnt = 0;
    int base = i * KNB;
    for (int z = z0; z <= z1; z++) {
        for (int y = y0; y <= y1; y++) {
            int crow = ((b * NC1 + z) * NC1 + y) * NC1;
            int t0 = g_cellstart[crow + x0];
            int t1 = g_cellstart[crow + x1 + 1];
            for (int tb = t0; tb < t1; tb += 32) {
                int t = tb + lane;
                bool hit = false; float d2 = 0.0f; int j = -1;
                if (t < t1) {
                    float4 c = g_ps_sorted[t];
                    float dot = fmaf(me.x, c.x, fmaf(me.y, c.y, me.z * c.z));
                    d2 = (me.w + c.w) - 2.0f * dot;
                    if (d2 < RR) { hit = true; j = g_sortidx[t]; }
                }
                unsigned mask = __ballot_sync(FULL, hit);
                int pos = cnt + __popc(mask & ((1u << lane) - 1u));
                if (hit && pos < KNB) {
                    g_nbr[base + pos]   = j;
                    g_nbrd2[base + pos] = d2;
                }
                int newcnt = cnt + __popc(mask);
                if (newcnt > KNB) {
                    // rare overflow: serial lex-(d2,idx) replacement, t-ascending
                    __syncwarp(FULL);
                    unsigned of = __ballot_sync(FULL, hit && pos >= KNB);
                    while (of) {
                        int src = __ffs(of) - 1;
                        float dd = __shfl_sync(FULL, d2, src);
                        int   jj = __shfl_sync(FULL, j, src);
                        if (lane == 0) {
                            int mxs = 0; float mxd = g_nbrd2[base]; int mxi = g_nbr[base];
                            for (int s = 1; s < KNB; s++) {
                                float d = g_nbrd2[base + s]; int id = g_nbr[base + s];
                                if (d > mxd || (d == mxd && id > mxi)) { mxd = d; mxi = id; mxs = s; }
                            }
                            if (dd < mxd || (dd == mxd && jj < mxi)) {
                                g_nbr[base + mxs] = jj; g_nbrd2[base + mxs] = dd;
                            }
                        }
                        __syncwarp(FULL);
                        of &= of - 1;
                    }
                    cnt = KNB;
                } else {
                    cnt = newcnt;
                }
            }
        }
    }
    int off = 0;
    if (lane == 0) {
        g_cnt[i] = cnt;
        off = atomicAdd(&g_ealloc, cnt);
    }
    off = __shfl_sync(FULL, off, 0);
    if (lane < cnt) g_epack[off + lane] = (i << 13) | g_nbr[base + lane];
}

// ---------------- edge-parallel MLP: pipelined, double-buffered, 4-acc FFMA2 ----
// 128 edges per 256-thread block; each thread: 32 CONSECUTIVE edges.
// One barrier per edge; next edge's loads overlap current edge's layer2.
#define EDGES_PER_BLK 128
__global__ void __launch_bounds__(256) k_mlp(const float* __restrict__ w2,
                                             const float* __restrict__ b2) {
    int E  = g_ealloc;
    int e0 = blockIdx.x * EDGES_PER_BLK;
    if (e0 >= E) return;
    int slot = threadIdx.x >> 6;       // 0..3
    int c    = threadIdx.x & 63;       // channel
    __shared__ __align__(16) float h1sm[2][4][CH];   // double buffer
    __shared__ float redsm[4][CH];
    __shared__ float redsm2[4][CH];

    // packed column of W2: pairs over the f (input) dimension
    u64 w2p[CH / 2];
#pragma unroll
    for (int f2 = 0; f2 < CH / 2; f2++)
        w2p[f2] = pack2(w2[(2 * f2) * CH + c], w2[(2 * f2 + 1) * CH + c]);
    float b2c = b2[c];

    int ebase = e0 + slot * (EDGES_PER_BLK / 4);   // this thread's 32 consecutive edges

    // prologue: edge 0
    bool act_cur = (ebase < E);
    int  i_cur = 0;
    {
        float h = 0.0f;
        if (act_cur) {
            int p = g_epack[ebase];
            i_cur = p >> 13;
            int j = p & 8191;
            h = g_Aj[j * CH + c] - g_Bi[i_cur * CH + c];
        }
        h1sm[0][slot][c] = (h >= 0.0f) ? h : 0.01f * h;
    }

    float acc = 0.0f, acc2 = 0.0f;
    int cur_i = -1; unsigned cur_mx = 0u;
#pragma unroll 1
    for (int it = 0; it < EDGES_PER_BLK / 4; it++) {
        int buf = it & 1;
        __syncthreads();
        // prefetch + stage next edge's h into the other buffer
        bool act_next = false; int i_next = 0;
        if (it + 1 < EDGES_PER_BLK / 4) {
            int e = ebase + it + 1;
            act_next = (e < E);
            float h = 0.0f;
            if (act_next) {
                int p = g_epack[e];
                i_next = p >> 13;
                int j = p & 8191;
                h = g_Aj[j * CH + c] - g_Bi[i_next * CH + c];
            }
            h1sm[1 - buf][slot][c] = (h >= 0.0f) ? h : 0.01f * h;
        }
        // layer2 on current buffer: float4 loads, 4 independent packed accumulators
        const float4* h1q = (const float4*)h1sm[buf][slot];
        u64 a0 = 0, a1 = 0, a2 = 0, a3 = 0;
#pragma unroll
        for (int f4 = 0; f4 < CH / 4; f4 += 2) {
            float4 hv0 = h1q[f4];
            float4 hv1 = h1q[f4 + 1];
            a0 = ffma2(pack2(hv0.x, hv0.y), w2p[2 * f4],     a0);
            a1 = ffma2(pack2(hv0.z, hv0.w), w2p[2 * f4 + 1], a1);
            a2 = ffma2(pack2(hv1.x, hv1.y), w2p[2 * f4 + 2], a2);
            a3 = ffma2(pack2(hv1.z, hv1.w), w2p[2 * f4 + 3], a3);
        }
        u64 s01 = fadd2(a0, a1);
        u64 s23 = fadd2(a2, a3);
        u64 st  = fadd2(s01, s23);
        float lo, hi; unpack2(st, lo, hi);
        float h2 = b2c + lo + hi;
        h2 = (h2 >= 0.0f) ? h2 : 0.01f * h2;
        if (act_cur) {
            acc  += h2;
            acc2  = fmaf(h2, h2, acc2);
            unsigned ord = ford(h2);
            if (i_cur != cur_i) {
                if (cur_i >= 0) atomicMax(&g_maxord[cur_i * CH + c], cur_mx);
                cur_i = i_cur; cur_mx = ord;
            } else if (ord > cur_mx) {
                cur_mx = ord;
            }
        }
        act_cur = act_next; i_cur = i_next;
    }
    if (cur_i >= 0) atomicMax(&g_maxord[cur_i * CH + c], cur_mx);
    redsm[slot][c]  = acc;
    redsm2[slot][c] = acc2;
    __syncthreads();
    if (slot == 0) {
        float s  = redsm[0][c]  + redsm[1][c]  + redsm[2][c]  + redsm[3][c];
        float s2 = redsm2[0][c] + redsm2[1][c] + redsm2[2][c] + redsm2[3][c];
        atomicAdd(&g_sum[c], s);
        atomicAdd(&g_sumsq[c], s2);
    }
}

// ---------------- BN affine on max + tuple passthrough + cellcnt cleanup -------
__global__ void __launch_bounds__(256) k_out(float* __restrict__ out,
                                             const float* __restrict__ gamma,
                                             const float* __restrict__ beta,
                                             const float* __restrict__ pos,
                                             const float* __restrict__ refl,
                                             const float* __restrict__ sf,
                                             int do_pass) {
    int g = threadIdx.x >> 6;
    int c = threadIdx.x & 63;
    int i = blockIdx.x * 4 + g;
    int cnt = g_cnt[i];
    float invE = 1.0f / (float)g_ealloc;
    float mean = g_sum[c] * invE;
    float var  = g_sumsq[c] * invE - mean * mean;
    if (var < 0.0f) var = 0.0f;
    float A = gamma[c] * rsqrtf(var + 1e-5f);
    float B = beta[c] - mean * A;
    unsigned mo = g_maxord[i * CH + c];
    g_maxord[i * CH + c] = 0u;                 // self-clean for next call
    out[i * CH + c] = (cnt > 0) ? fmaf(dord(mo), A, B) : NEGV;

    int idx = blockIdx.x * 256 + threadIdx.x;
    if (idx < NCELLS) g_cellcnt[idx] = 0;      // restore zero-state invariant
    if (!do_pass) return;
    if (idx < 3 * NPTS) {
        out[POS_OFF + idx] = pos[idx];
    } else if (idx < 4 * NPTS) {
        int j = idx - 3 * NPTS;
        out[BATCH_OFF + j] = (float)g_batch[j];
    } else if (idx < 5 * NPTS) {
        int j = idx - 4 * NPTS;
        out[REF_OFF + j] = refl[j];
    } else if (idx < 5 * NPTS + 4) {
        int j = idx - 5 * NPTS;
        out[SF_OFF + j] = sf[j];
    }
}

extern "C" void kernel_launch(void* const* d_in, const int* in_sizes, int n_in,
                              void* d_out, int out_size) {
    const float* x     = (const float*)d_in[0];
    const float* pos   = (const float*)d_in[1];
    const float* refl  = (const float*)d_in[2];
    const float* sf    = (const float*)d_in[3];
    const float* w1    = (const float*)d_in[4];
    const float* b1    = (const float*)d_in[5];
    const float* w2    = (const float*)d_in[6];
    const float* b2    = (const float*)d_in[7];
    const float* gamma = (const float*)d_in[8];
    const float* beta  = (const float*)d_in[9];
    const int*   braw  = (const int*)d_in[10];
    float* out = (float*)d_out;

    k_prep<<<NPTS / 4, 256>>>(pos, refl, sf, braw, x, w1, b1);
    k_scatter<<<NPTS / 256, 256>>>();
    k_nbr<<<NPTS / 8, 256>>>();
    k_mlp<<<NPTS * KNB / EDGES_PER_BLK, 256>>>(w2, b2);
    int do_pass = (out_size >= TOTAL_OUT) ? 1 : 0;
    k_out<<<NPTS / 4, 256>>>(out, gamma, beta, pos, refl, sf, do_pass);
}